// round 1
// baseline (speedup 1.0000x reference)
#include <cuda_runtime.h>

// ---------------- problem constants ----------------
#define BB 32
#define TT 64
#define NFR 2048          // B*T
#define AA 6
#define LL 32
#define HH 128
#define FD 256

// ---------------- scratch (static device memory; no allocations) ----------------
__device__ float g_b1[(size_t)NFR * 32 * 32 * 32];   // conv1 out
__device__ float g_b2[(size_t)NFR * 64 * 16 * 16];   // conv2 out
__device__ float g_b3[(size_t)NFR * 128 * 8 * 8];    // conv3 out
__device__ float g_b4[(size_t)NFR * 256 * 4 * 4];    // conv4 out
__device__ float g_feats[(size_t)NFR * FD];          // encoder features
__device__ float g_w1T[48 * 32];
__device__ float g_w2T[32 * 16 * 64];
__device__ float g_w3T[64 * 16 * 128];
__device__ float g_w4T[128 * 16 * 256];
__device__ float g_fcT[4096 * 256];

// packed fp32x2 FMA (sm_100+): d = a*b + c
__device__ __forceinline__ float2 ffma2(float2 a, float2 b, float2 c) {
#if defined(__CUDA_ARCH__) && (__CUDA_ARCH__ >= 1000)
    unsigned long long ua = *reinterpret_cast<unsigned long long*>(&a);
    unsigned long long ub = *reinterpret_cast<unsigned long long*>(&b);
    unsigned long long uc = *reinterpret_cast<unsigned long long*>(&c);
    unsigned long long ud;
    asm("fma.rn.f32x2 %0, %1, %2, %3;" : "=l"(ud) : "l"(ua), "l"(ub), "l"(uc));
    return *reinterpret_cast<float2*>(&ud);
#else
    c.x = fmaf(a.x, b.x, c.x);
    c.y = fmaf(a.y, b.y, c.y);
    return c;
#endif
}

// ---------------- weight transpose: w[oc][ict] -> wT[ict][oc] ----------------
__global__ void transpose_kernel(const float* __restrict__ w, float* __restrict__ wT,
                                 int OC, int ICT) {
    int total = OC * ICT;
    for (int idx = blockIdx.x * blockDim.x + threadIdx.x; idx < total;
         idx += gridDim.x * blockDim.x) {
        int oc = idx / ICT;
        int t  = idx % ICT;
        wT[t * OC + oc] = w[idx];
    }
}

// ---------------- conv1: (N,3,64,64) -> (N,32,32,32) ----------------
// grid (NFR, 4 row-strips), 256 threads. Each thread: 1 output position, all 32 oc.
__global__ void conv1_kernel(const float* __restrict__ in, const float* __restrict__ wT,
                             const float* __restrict__ bias, float* __restrict__ out) {
    __shared__ __align__(16) float in_s[3 * 18 * 64];
    __shared__ __align__(16) float w_s[48 * 32];
    int tid = threadIdx.x;
    int n = blockIdx.x, s = blockIdx.y;
    const float* f = in + (size_t)n * 3 * 64 * 64;

    for (int i = tid; i < 3 * 18 * 64; i += 256) {
        int ch = i / (18 * 64);
        int r  = (i / 64) % 18;
        int c  = i % 64;
        int iy = 16 * s - 1 + r;
        in_s[i] = (iy >= 0 && iy < 64) ? f[ch * 4096 + iy * 64 + c] : 0.f;
    }
    for (int i = tid; i < 1536; i += 256) w_s[i] = wT[i];
    __syncthreads();

    int oyl = tid / 32, ox = tid % 32;
    float2 acc[16];
#pragma unroll
    for (int o = 0; o < 16; ++o) acc[o] = make_float2(0.f, 0.f);

    for (int ch = 0; ch < 3; ++ch) {
        for (int ky = 0; ky < 4; ++ky) {
            int r = 2 * oyl + ky;
            for (int kx = 0; kx < 4; ++kx) {
                int ix = 2 * ox + kx - 1;
                float v = (ix >= 0 && ix < 64) ? in_s[(ch * 18 + r) * 64 + ix] : 0.f;
                float2 v2 = make_float2(v, v);
                const float2* wr =
                    reinterpret_cast<const float2*>(&w_s[(ch * 16 + ky * 4 + kx) * 32]);
#pragma unroll
                for (int o = 0; o < 16; ++o) acc[o] = ffma2(v2, wr[o], acc[o]);
            }
        }
    }
    int oy = s * 8 + oyl;
#pragma unroll
    for (int o = 0; o < 16; ++o) {
        float r0 = acc[o].x + bias[2 * o];
        float r1 = acc[o].y + bias[2 * o + 1];
        out[(((size_t)n * 32 + 2 * o) * 32 + oy) * 32 + ox]     = r0 > 0.f ? r0 : 0.f;
        out[(((size_t)n * 32 + 2 * o + 1) * 32 + oy) * 32 + ox] = r1 > 0.f ? r1 : 0.f;
    }
}

// ---------------- generic conv (layers 2-4), stride 2, k=4, pad 1, + ReLU ----------------
// block = one frame, 256 threads = (OH*OH positions) x (OC/OCPT groups)
template <int IC, int IH, int OC, int ICC, int OCPT>
__global__ void conv_kernel(const float* __restrict__ in, const float* __restrict__ wT,
                            const float* __restrict__ bias, float* __restrict__ out) {
    constexpr int OH  = IH / 2;
    constexpr int POS = OH * OH;
    __shared__ __align__(16) float in_s[ICC * IH * IH];
    __shared__ __align__(16) float w_s[ICC * 16 * OC];

    int tid = threadIdx.x;
    int n = blockIdx.x;
    int pos = tid % POS;
    int g = tid / POS;
    int oy = pos / OH, ox = pos % OH;
    int oc0 = g * OCPT;

    float2 acc[OCPT / 2];
#pragma unroll
    for (int o = 0; o < OCPT / 2; ++o) acc[o] = make_float2(0.f, 0.f);

    const float* in_frame = in + (size_t)n * IC * IH * IH;

    for (int c0 = 0; c0 < IC; c0 += ICC) {
        __syncthreads();
        for (int i = tid; i < ICC * IH * IH; i += 256)
            in_s[i] = in_frame[(size_t)c0 * IH * IH + i];
        for (int i = tid; i < ICC * 16 * OC; i += 256)
            w_s[i] = wT[(size_t)c0 * 16 * OC + i];
        __syncthreads();

        for (int icl = 0; icl < ICC; ++icl) {
            for (int ky = 0; ky < 4; ++ky) {
                int iy = 2 * oy + ky - 1;
                if (iy < 0 || iy >= IH) continue;
                for (int kx = 0; kx < 4; ++kx) {
                    int ix = 2 * ox + kx - 1;
                    if (ix < 0 || ix >= IH) continue;
                    float v = in_s[(icl * IH + iy) * IH + ix];
                    float2 v2 = make_float2(v, v);
                    const float2* wr = reinterpret_cast<const float2*>(
                        &w_s[((icl * 16) + ky * 4 + kx) * OC + oc0]);
#pragma unroll
                    for (int o = 0; o < OCPT / 2; ++o) acc[o] = ffma2(v2, wr[o], acc[o]);
                }
            }
        }
    }

    size_t obase = ((size_t)n * OC + oc0) * POS + pos;
#pragma unroll
    for (int o = 0; o < OCPT / 2; ++o) {
        float r0 = acc[o].x + bias[oc0 + 2 * o];
        float r1 = acc[o].y + bias[oc0 + 2 * o + 1];
        out[obase + (size_t)(2 * o) * POS]     = r0 > 0.f ? r0 : 0.f;
        out[obase + (size_t)(2 * o + 1) * POS] = r1 > 0.f ? r1 : 0.f;
    }
}

// ---------------- FC: feats[n][fd] = b4[n][:4096] . fcT[:,fd] + b ----------------
__global__ void fc_kernel(const float* __restrict__ inp, const float* __restrict__ fcT,
                          const float* __restrict__ fcb, float* __restrict__ feats) {
    constexpr int NPB = 8, KC = 128;
    __shared__ float in_s[NPB][KC];
    int tid = threadIdx.x;
    int n0 = blockIdx.x * NPB;
    float acc[NPB];
#pragma unroll
    for (int nn = 0; nn < NPB; ++nn) acc[nn] = 0.f;

    for (int k0 = 0; k0 < 4096; k0 += KC) {
        __syncthreads();
        for (int i = tid; i < NPB * KC; i += 256) {
            int nn = i / KC, kk = i % KC;
            in_s[nn][kk] = inp[(size_t)(n0 + nn) * 4096 + k0 + kk];
        }
        __syncthreads();
        for (int kk = 0; kk < KC; ++kk) {
            float w = fcT[(size_t)(k0 + kk) * 256 + tid];
#pragma unroll
            for (int nn = 0; nn < NPB; ++nn) acc[nn] = fmaf(in_s[nn][kk], w, acc[nn]);
        }
    }
    float bv = fcb[tid];
#pragma unroll
    for (int nn = 0; nn < NPB; ++nn)
        feats[(size_t)(n0 + nn) * 256 + tid] = acc[nn] + bv;
}

// ---------------- sequential scan: GRU + prior/post + reparam ----------------
// one block per batch element, 384 threads (one per gate output)
__global__ void scan_kernel(const float* __restrict__ actions, const float* __restrict__ feats,
                            const float* __restrict__ wih, const float* __restrict__ whh,
                            const float* __restrict__ bih, const float* __restrict__ bhh,
                            const float* __restrict__ pw, const float* __restrict__ pb,
                            const float* __restrict__ qw, const float* __restrict__ qb,
                            const float* __restrict__ eps, float* __restrict__ out) {
    int b = blockIdx.x, tid = threadIdx.x;
    __shared__ float x_s[40];
    __shared__ __align__(16) float h_s[HH];
    __shared__ __align__(16) float f_s[FD];
    __shared__ float gi_s[3 * HH], gh_s[3 * HH];
    __shared__ float p_s[2 * LL], q_s[2 * LL];

    if (tid < LL) x_s[tid] = 0.f;
    if (tid < HH) h_s[tid] = 0.f;

    float* out_mup = out;
    float* out_lvp = out + (size_t)NFR * LL;
    float* out_muq = out + (size_t)NFR * LL * 2;
    float* out_lvq = out + (size_t)NFR * LL * 3;
    float* out_h   = out + (size_t)NFR * LL * 4;
    float* out_z   = out + (size_t)NFR * LL * 4 + (size_t)NFR * HH;

    for (int t = 0; t < TT; ++t) {
        int bt = b * TT + t;
        if (tid >= LL && tid < LL + AA) x_s[tid] = actions[(size_t)bt * AA + (tid - LL)];
        if (tid < FD) f_s[tid] = feats[(size_t)bt * FD + tid];
        __syncthreads();

        {   // gi[j], gh[j] for j = tid (0..383)
            int j = tid;
            float gi = bih[j];
            const float* wr = wih + j * (LL + AA);
#pragma unroll
            for (int k = 0; k < LL + AA; ++k) gi = fmaf(x_s[k], wr[k], gi);

            float gh = bhh[j];
            const float4* w4 = reinterpret_cast<const float4*>(whh + (size_t)j * HH);
            float s0 = 0.f, s1 = 0.f, s2 = 0.f, s3 = 0.f;
#pragma unroll
            for (int k = 0; k < HH / 4; ++k) {
                float4 w = w4[k];
                s0 = fmaf(h_s[4 * k + 0], w.x, s0);
                s1 = fmaf(h_s[4 * k + 1], w.y, s1);
                s2 = fmaf(h_s[4 * k + 2], w.z, s2);
                s3 = fmaf(h_s[4 * k + 3], w.w, s3);
            }
            gh += (s0 + s1) + (s2 + s3);
            gi_s[j] = gi;
            gh_s[j] = gh;
        }
        __syncthreads();

        if (tid < HH) {
            int u = tid;
            float r  = 1.f / (1.f + expf(-(gi_s[u] + gh_s[u])));
            float zz = 1.f / (1.f + expf(-(gi_s[u + HH] + gh_s[u + HH])));
            float nn = tanhf(gi_s[u + 2 * HH] + r * gh_s[u + 2 * HH]);
            h_s[u] = (1.f - zz) * nn + zz * h_s[u];
        }
        __syncthreads();

        if (tid < 2 * LL) {   // prior head
            int j = tid;
            const float4* w4 = reinterpret_cast<const float4*>(pw + (size_t)j * HH);
            float s0 = 0.f, s1 = 0.f, s2 = 0.f, s3 = 0.f;
#pragma unroll
            for (int k = 0; k < HH / 4; ++k) {
                float4 w = w4[k];
                s0 = fmaf(h_s[4 * k + 0], w.x, s0);
                s1 = fmaf(h_s[4 * k + 1], w.y, s1);
                s2 = fmaf(h_s[4 * k + 2], w.z, s2);
                s3 = fmaf(h_s[4 * k + 3], w.w, s3);
            }
            p_s[j] = pb[j] + (s0 + s1) + (s2 + s3);
        } else if (tid < 4 * LL) {   // posterior head: [h, f] (128+256)
            int j = tid - 2 * LL;
            const float4* w4 = reinterpret_cast<const float4*>(qw + (size_t)j * (HH + FD));
            float s0 = 0.f, s1 = 0.f, s2 = 0.f, s3 = 0.f;
#pragma unroll
            for (int k = 0; k < HH / 4; ++k) {
                float4 w = w4[k];
                s0 = fmaf(h_s[4 * k + 0], w.x, s0);
                s1 = fmaf(h_s[4 * k + 1], w.y, s1);
                s2 = fmaf(h_s[4 * k + 2], w.z, s2);
                s3 = fmaf(h_s[4 * k + 3], w.w, s3);
            }
#pragma unroll
            for (int k = 0; k < FD / 4; ++k) {
                float4 w = w4[HH / 4 + k];
                s0 = fmaf(f_s[4 * k + 0], w.x, s0);
                s1 = fmaf(f_s[4 * k + 1], w.y, s1);
                s2 = fmaf(f_s[4 * k + 2], w.z, s2);
                s3 = fmaf(f_s[4 * k + 3], w.w, s3);
            }
            q_s[j] = qb[j] + (s0 + s1) + (s2 + s3);
        }
        __syncthreads();

        if (tid < HH) out_h[(size_t)bt * HH + tid] = h_s[tid];
        if (tid < LL) {
            int l = tid;
            out_mup[(size_t)bt * LL + l] = p_s[l];
            out_lvp[(size_t)bt * LL + l] = p_s[l + LL];
            float muq = q_s[l], lvq = q_s[l + LL];
            out_muq[(size_t)bt * LL + l] = muq;
            out_lvq[(size_t)bt * LL + l] = lvq;
            float z = muq + expf(0.5f * lvq) * eps[(size_t)bt * LL + l];
            out_z[(size_t)bt * LL + l] = z;
            x_s[l] = z;   // feeds next step's GRU input
        }
        __syncthreads();
    }
}

// ---------------- launch ----------------
extern "C" void kernel_launch(void* const* d_in, const int* in_sizes, int n_in,
                              void* d_out, int out_size) {
    const float* states  = (const float*)d_in[0];
    const float* actions = (const float*)d_in[1];
    const float* c1_w = (const float*)d_in[2];
    const float* c1_b = (const float*)d_in[3];
    const float* c2_w = (const float*)d_in[4];
    const float* c2_b = (const float*)d_in[5];
    const float* c3_w = (const float*)d_in[6];
    const float* c3_b = (const float*)d_in[7];
    const float* c4_w = (const float*)d_in[8];
    const float* c4_b = (const float*)d_in[9];
    const float* fc_w = (const float*)d_in[10];
    const float* fc_b = (const float*)d_in[11];
    const float* gru_wih = (const float*)d_in[12];
    const float* gru_whh = (const float*)d_in[13];
    const float* gru_bih = (const float*)d_in[14];
    const float* gru_bhh = (const float*)d_in[15];
    const float* prior_w = (const float*)d_in[16];
    const float* prior_b = (const float*)d_in[17];
    const float* post_w  = (const float*)d_in[18];
    const float* post_b  = (const float*)d_in[19];
    const float* eps     = (const float*)d_in[20];
    float* out = (float*)d_out;

    float *b1, *b2, *b3, *b4, *feats, *w1T, *w2T, *w3T, *w4T, *fcT;
    cudaGetSymbolAddress((void**)&b1, g_b1);
    cudaGetSymbolAddress((void**)&b2, g_b2);
    cudaGetSymbolAddress((void**)&b3, g_b3);
    cudaGetSymbolAddress((void**)&b4, g_b4);
    cudaGetSymbolAddress((void**)&feats, g_feats);
    cudaGetSymbolAddress((void**)&w1T, g_w1T);
    cudaGetSymbolAddress((void**)&w2T, g_w2T);
    cudaGetSymbolAddress((void**)&w3T, g_w3T);
    cudaGetSymbolAddress((void**)&w4T, g_w4T);
    cudaGetSymbolAddress((void**)&fcT, g_fcT);

    transpose_kernel<<<8, 256>>>(c1_w, w1T, 32, 48);
    transpose_kernel<<<32, 256>>>(c2_w, w2T, 64, 512);
    transpose_kernel<<<64, 256>>>(c3_w, w3T, 128, 1024);
    transpose_kernel<<<128, 256>>>(c4_w, w4T, 256, 2048);
    transpose_kernel<<<256, 256>>>(fc_w, fcT, 256, 4096);

    conv1_kernel<<<dim3(NFR, 4), 256>>>(states, w1T, c1_b, b1);
    conv_kernel<32, 32, 64, 4, 64><<<NFR, 256>>>(b1, w2T, c2_b, b2);
    conv_kernel<64, 16, 128, 4, 32><<<NFR, 256>>>(b2, w3T, c3_b, b3);
    conv_kernel<128, 8, 256, 2, 16><<<NFR, 256>>>(b3, w4T, c4_b, b4);
    fc_kernel<<<NFR / 8, 256>>>(b4, fcT, fc_b, feats);

    scan_kernel<<<BB, 384>>>(actions, feats, gru_wih, gru_whh, gru_bih, gru_bhh,
                             prior_w, prior_b, post_w, post_b, eps, out);
}

// round 2
// speedup vs baseline: 1.1370x; 1.1370x over previous
#include <cuda_runtime.h>

// ---------------- problem constants ----------------
#define BB 32
#define TT 64
#define NFR 2048          // B*T
#define AA 6
#define LL 32
#define HH 128
#define FD 256

// ---------------- scratch (static device memory; no allocations) ----------------
__device__ float g_b1[(size_t)NFR * 32 * 32 * 32];   // conv1 out
__device__ float g_b2[(size_t)NFR * 64 * 16 * 16];   // conv2 out
__device__ float g_b3[(size_t)NFR * 128 * 8 * 8];    // conv3 out
__device__ float g_b4[(size_t)NFR * 256 * 4 * 4];    // conv4 out
__device__ float g_feats[(size_t)NFR * FD];          // encoder features
__device__ float g_w1T[48 * 32];
__device__ float g_w2T[32 * 16 * 64];
__device__ float g_w3T[64 * 16 * 128];
__device__ float g_w4T[128 * 16 * 256];
__device__ float g_fcT[4096 * 256];

// packed fp32x2 FMA (sm_100+): d = a*b + c
__device__ __forceinline__ float2 ffma2(float2 a, float2 b, float2 c) {
#if defined(__CUDA_ARCH__) && (__CUDA_ARCH__ >= 1000)
    unsigned long long ua = *reinterpret_cast<unsigned long long*>(&a);
    unsigned long long ub = *reinterpret_cast<unsigned long long*>(&b);
    unsigned long long uc = *reinterpret_cast<unsigned long long*>(&c);
    unsigned long long ud;
    asm("fma.rn.f32x2 %0, %1, %2, %3;" : "=l"(ud) : "l"(ua), "l"(ub), "l"(uc));
    return *reinterpret_cast<float2*>(&ud);
#else
    c.x = fmaf(a.x, b.x, c.x);
    c.y = fmaf(a.y, b.y, c.y);
    return c;
#endif
}

// ---------------- weight transpose: w[oc][ict] -> wT[ict][oc] ----------------
__global__ void transpose_kernel(const float* __restrict__ w, float* __restrict__ wT,
                                 int OC, int ICT) {
    int total = OC * ICT;
    for (int idx = blockIdx.x * blockDim.x + threadIdx.x; idx < total;
         idx += gridDim.x * blockDim.x) {
        int oc = idx / ICT;
        int t  = idx % ICT;
        wT[t * OC + oc] = w[idx];
    }
}

// ---------------- conv1: (N,3,64,64) -> (N,32,32,32) ----------------
__global__ void conv1_kernel(const float* __restrict__ in, const float* __restrict__ wT,
                             const float* __restrict__ bias, float* __restrict__ out) {
    __shared__ __align__(16) float in_s[3 * 18 * 64];
    __shared__ __align__(16) float w_s[48 * 32];
    int tid = threadIdx.x;
    int n = blockIdx.x, s = blockIdx.y;
    const float* f = in + (size_t)n * 3 * 64 * 64;

    for (int i = tid; i < 3 * 18 * 64; i += 256) {
        int ch = i / (18 * 64);
        int r  = (i / 64) % 18;
        int c  = i % 64;
        int iy = 16 * s - 1 + r;
        in_s[i] = (iy >= 0 && iy < 64) ? f[ch * 4096 + iy * 64 + c] : 0.f;
    }
    for (int i = tid; i < 1536; i += 256) w_s[i] = wT[i];
    __syncthreads();

    int oyl = tid / 32, ox = tid % 32;
    float2 acc[16];
#pragma unroll
    for (int o = 0; o < 16; ++o) acc[o] = make_float2(0.f, 0.f);

    for (int ch = 0; ch < 3; ++ch) {
        for (int ky = 0; ky < 4; ++ky) {
            int r = 2 * oyl + ky;
            for (int kx = 0; kx < 4; ++kx) {
                int ix = 2 * ox + kx - 1;
                float v = (ix >= 0 && ix < 64) ? in_s[(ch * 18 + r) * 64 + ix] : 0.f;
                float2 v2 = make_float2(v, v);
                const float2* wr =
                    reinterpret_cast<const float2*>(&w_s[(ch * 16 + ky * 4 + kx) * 32]);
#pragma unroll
                for (int o = 0; o < 16; ++o) acc[o] = ffma2(v2, wr[o], acc[o]);
            }
        }
    }
    int oy = s * 8 + oyl;
#pragma unroll
    for (int o = 0; o < 16; ++o) {
        float r0 = acc[o].x + bias[2 * o];
        float r1 = acc[o].y + bias[2 * o + 1];
        out[(((size_t)n * 32 + 2 * o) * 32 + oy) * 32 + ox]     = r0 > 0.f ? r0 : 0.f;
        out[(((size_t)n * 32 + 2 * o + 1) * 32 + oy) * 32 + ox] = r1 > 0.f ? r1 : 0.f;
    }
}

// ---------------- generic conv (layers 2-4): parity-split smem, register-blocked ----
// Layout in smem per (channel, frame) plane: row r in [0, IH+2), parity p, x2 in [0, S)
//   idx = (y+1)*2*S + (x&1)*S + (x>>1) + 1 ; borders stay zero.
// Thread: P positions (g = lane + 32p over F*POS), OCW/2 float2 output channels.
template <int IC, int IH, int OC, int F, int OCW, int ICC, int S, int PS, int NTH>
__global__ void __launch_bounds__(NTH)
convN_kernel(const float* __restrict__ in, const float* __restrict__ wT,
             const float* __restrict__ bias, float* __restrict__ out) {
    constexpr int OW  = IH / 2;
    constexpr int POS = OW * OW;
    constexpr int P   = F * POS / 32;
    constexpr int OCP = OCW / 2;

    __shared__ __align__(16) float in_s[ICC * F * PS];
    __shared__ __align__(16) float w_s[ICC * 16 * OC];

    const int tid = threadIdx.x, lane = tid & 31, warp = tid >> 5;
    const int n0  = blockIdx.x * F;
    const int oc0 = warp * OCW;

    for (int i = tid; i < ICC * F * PS; i += NTH) in_s[i] = 0.f;

    int pbase[P];
#pragma unroll
    for (int p = 0; p < P; ++p) {
        int g = lane + 32 * p;
        int fr = g / POS, pg = g % POS;
        int oy = pg / OW, ox = pg % OW;
        pbase[p] = fr * PS + oy * 4 * S + ox;
    }

    float2 acc[P][OCP];
#pragma unroll
    for (int p = 0; p < P; ++p)
#pragma unroll
        for (int o = 0; o < OCP; ++o) acc[p][o] = make_float2(0.f, 0.f);

    for (int c0 = 0; c0 < IC; c0 += ICC) {
        __syncthreads();
        for (int i = tid; i < ICC * F * IH * IH; i += NTH) {
            int x  = i % IH;
            int y  = (i / IH) % IH;
            int fr = (i / (IH * IH)) % F;
            int c  = i / (IH * IH * F);
            float v = in[(((size_t)(n0 + fr)) * IC + (c0 + c)) * (IH * IH) + y * IH + x];
            in_s[(c * F + fr) * PS + (y + 1) * 2 * S + (x & 1) * S + (x >> 1) + 1] = v;
        }
        for (int i = tid; i < ICC * 16 * OC; i += NTH)
            w_s[i] = wT[(size_t)c0 * 16 * OC + i];
        __syncthreads();

#pragma unroll
        for (int icl = 0; icl < ICC; ++icl) {
            const float* A = in_s + icl * F * PS;
#pragma unroll
            for (int t = 0; t < 16; ++t) {
                const int ky = t >> 2, kx = t & 3;
                // kx -> (parity, dx): 0:(1,0) 1:(0,1) 2:(1,1) 3:(0,2)
                const int par = (kx == 0 || kx == 2) ? 1 : 0;
                const int dx  = (kx == 0) ? 0 : ((kx == 3) ? 2 : 1);
                const int koff = ky * 2 * S + par * S + dx;
                const float2* wr =
                    reinterpret_cast<const float2*>(&w_s[(icl * 16 + t) * OC + oc0]);
                float2 wv[OCP];
#pragma unroll
                for (int o = 0; o < OCP; ++o) wv[o] = wr[o];
#pragma unroll
                for (int p = 0; p < P; ++p) {
                    float a = A[pbase[p] + koff];
                    float2 a2 = make_float2(a, a);
#pragma unroll
                    for (int o = 0; o < OCP; ++o) acc[p][o] = ffma2(a2, wv[o], acc[p][o]);
                }
            }
        }
    }

#pragma unroll
    for (int p = 0; p < P; ++p) {
        int g = lane + 32 * p;
        int fr = g / POS, pg = g % POS;
        size_t base = (((size_t)(n0 + fr)) * OC + oc0) * POS + pg;
#pragma unroll
        for (int o = 0; o < OCP; ++o) {
            float r0 = acc[p][o].x + bias[oc0 + 2 * o];
            float r1 = acc[p][o].y + bias[oc0 + 2 * o + 1];
            out[base + (size_t)(2 * o) * POS]     = fmaxf(r0, 0.f);
            out[base + (size_t)(2 * o + 1) * POS] = fmaxf(r1, 0.f);
        }
    }
}

// ---------------- FC: feats[n][fd] = b4[n][:4096] . fcT[:,fd] + b ----------------
// 256 threads: tid%128 -> fd float2 column, tid/128 -> frame half. 16 frames/block.
__global__ void __launch_bounds__(256) fc_kernel(const float* __restrict__ inp,
                                                 const float* __restrict__ fcT,
                                                 const float* __restrict__ fcb,
                                                 float* __restrict__ feats) {
    constexpr int NPB = 16, KC = 128;
    __shared__ float in_s[NPB * KC];
    int tid = threadIdx.x;
    int fd2 = tid & 127;
    int half = tid >> 7;
    int n0 = blockIdx.x * NPB;
    const float2* fcT2 = reinterpret_cast<const float2*>(fcT);

    float2 acc[8];
#pragma unroll
    for (int nn = 0; nn < 8; ++nn) acc[nn] = make_float2(0.f, 0.f);

    for (int k0 = 0; k0 < 4096; k0 += KC) {
        __syncthreads();
        for (int i = tid; i < NPB * KC; i += 256) {
            int nn = i / KC, kk = i % KC;
            in_s[i] = inp[(size_t)(n0 + nn) * 4096 + k0 + kk];
        }
        __syncthreads();
        for (int kk = 0; kk < KC; ++kk) {
            float2 w = fcT2[(size_t)(k0 + kk) * 128 + fd2];
#pragma unroll
            for (int nn = 0; nn < 8; ++nn) {
                float v = in_s[(half * 8 + nn) * KC + kk];
                acc[nn] = ffma2(make_float2(v, v), w, acc[nn]);
            }
        }
    }
    float2 bv = reinterpret_cast<const float2*>(fcb)[fd2];
#pragma unroll
    for (int nn = 0; nn < 8; ++nn) {
        size_t o = (size_t)(n0 + half * 8 + nn) * 256 + 2 * fd2;
        feats[o]     = acc[nn].x + bv.x;
        feats[o + 1] = acc[nn].y + bv.y;
    }
}

// ---------------- sequential scan: GRU + prior/post + reparam ----------------
__global__ void scan_kernel(const float* __restrict__ actions, const float* __restrict__ feats,
                            const float* __restrict__ wih, const float* __restrict__ whh,
                            const float* __restrict__ bih, const float* __restrict__ bhh,
                            const float* __restrict__ pw, const float* __restrict__ pb,
                            const float* __restrict__ qw, const float* __restrict__ qb,
                            const float* __restrict__ eps, float* __restrict__ out) {
    int b = blockIdx.x, tid = threadIdx.x;
    __shared__ float x_s[40];
    __shared__ __align__(16) float h_s[HH];
    __shared__ __align__(16) float f_s[FD];
    __shared__ float gi_s[3 * HH], gh_s[3 * HH];
    __shared__ float p_s[2 * LL], q_s[2 * LL];

    if (tid < LL) x_s[tid] = 0.f;
    if (tid < HH) h_s[tid] = 0.f;

    float* out_mup = out;
    float* out_lvp = out + (size_t)NFR * LL;
    float* out_muq = out + (size_t)NFR * LL * 2;
    float* out_lvq = out + (size_t)NFR * LL * 3;
    float* out_h   = out + (size_t)NFR * LL * 4;
    float* out_z   = out + (size_t)NFR * LL * 4 + (size_t)NFR * HH;

    for (int t = 0; t < TT; ++t) {
        int bt = b * TT + t;
        if (tid >= LL && tid < LL + AA) x_s[tid] = actions[(size_t)bt * AA + (tid - LL)];
        if (tid < FD) f_s[tid] = feats[(size_t)bt * FD + tid];
        __syncthreads();

        {
            int j = tid;
            float gi = bih[j];
            const float* wr = wih + j * (LL + AA);
#pragma unroll
            for (int k = 0; k < LL + AA; ++k) gi = fmaf(x_s[k], wr[k], gi);

            float gh = bhh[j];
            const float4* w4 = reinterpret_cast<const float4*>(whh + (size_t)j * HH);
            float s0 = 0.f, s1 = 0.f, s2 = 0.f, s3 = 0.f;
#pragma unroll
            for (int k = 0; k < HH / 4; ++k) {
                float4 w = w4[k];
                s0 = fmaf(h_s[4 * k + 0], w.x, s0);
                s1 = fmaf(h_s[4 * k + 1], w.y, s1);
                s2 = fmaf(h_s[4 * k + 2], w.z, s2);
                s3 = fmaf(h_s[4 * k + 3], w.w, s3);
            }
            gh += (s0 + s1) + (s2 + s3);
            gi_s[j] = gi;
            gh_s[j] = gh;
        }
        __syncthreads();

        if (tid < HH) {
            int u = tid;
            float r  = 1.f / (1.f + expf(-(gi_s[u] + gh_s[u])));
            float zz = 1.f / (1.f + expf(-(gi_s[u + HH] + gh_s[u + HH])));
            float nn = tanhf(gi_s[u + 2 * HH] + r * gh_s[u + 2 * HH]);
            h_s[u] = (1.f - zz) * nn + zz * h_s[u];
        }
        __syncthreads();

        if (tid < 2 * LL) {
            int j = tid;
            const float4* w4 = reinterpret_cast<const float4*>(pw + (size_t)j * HH);
            float s0 = 0.f, s1 = 0.f, s2 = 0.f, s3 = 0.f;
#pragma unroll
            for (int k = 0; k < HH / 4; ++k) {
                float4 w = w4[k];
                s0 = fmaf(h_s[4 * k + 0], w.x, s0);
                s1 = fmaf(h_s[4 * k + 1], w.y, s1);
                s2 = fmaf(h_s[4 * k + 2], w.z, s2);
                s3 = fmaf(h_s[4 * k + 3], w.w, s3);
            }
            p_s[j] = pb[j] + (s0 + s1) + (s2 + s3);
        } else if (tid < 4 * LL) {
            int j = tid - 2 * LL;
            const float4* w4 = reinterpret_cast<const float4*>(qw + (size_t)j * (HH + FD));
            float s0 = 0.f, s1 = 0.f, s2 = 0.f, s3 = 0.f;
#pragma unroll
            for (int k = 0; k < HH / 4; ++k) {
                float4 w = w4[k];
                s0 = fmaf(h_s[4 * k + 0], w.x, s0);
                s1 = fmaf(h_s[4 * k + 1], w.y, s1);
                s2 = fmaf(h_s[4 * k + 2], w.z, s2);
                s3 = fmaf(h_s[4 * k + 3], w.w, s3);
            }
#pragma unroll
            for (int k = 0; k < FD / 4; ++k) {
                float4 w = w4[HH / 4 + k];
                s0 = fmaf(f_s[4 * k + 0], w.x, s0);
                s1 = fmaf(f_s[4 * k + 1], w.y, s1);
                s2 = fmaf(f_s[4 * k + 2], w.z, s2);
                s3 = fmaf(f_s[4 * k + 3], w.w, s3);
            }
            q_s[j] = qb[j] + (s0 + s1) + (s2 + s3);
        }
        __syncthreads();

        if (tid < HH) out_h[(size_t)bt * HH + tid] = h_s[tid];
        if (tid < LL) {
            int l = tid;
            out_mup[(size_t)bt * LL + l] = p_s[l];
            out_lvp[(size_t)bt * LL + l] = p_s[l + LL];
            float muq = q_s[l], lvq = q_s[l + LL];
            out_muq[(size_t)bt * LL + l] = muq;
            out_lvq[(size_t)bt * LL + l] = lvq;
            float z = muq + expf(0.5f * lvq) * eps[(size_t)bt * LL + l];
            out_z[(size_t)bt * LL + l] = z;
            x_s[l] = z;
        }
        __syncthreads();
    }
}

// ---------------- launch ----------------
extern "C" void kernel_launch(void* const* d_in, const int* in_sizes, int n_in,
                              void* d_out, int out_size) {
    const float* states  = (const float*)d_in[0];
    const float* actions = (const float*)d_in[1];
    const float* c1_w = (const float*)d_in[2];
    const float* c1_b = (const float*)d_in[3];
    const float* c2_w = (const float*)d_in[4];
    const float* c2_b = (const float*)d_in[5];
    const float* c3_w = (const float*)d_in[6];
    const float* c3_b = (const float*)d_in[7];
    const float* c4_w = (const float*)d_in[8];
    const float* c4_b = (const float*)d_in[9];
    const float* fc_w = (const float*)d_in[10];
    const float* fc_b = (const float*)d_in[11];
    const float* gru_wih = (const float*)d_in[12];
    const float* gru_whh = (const float*)d_in[13];
    const float* gru_bih = (const float*)d_in[14];
    const float* gru_bhh = (const float*)d_in[15];
    const float* prior_w = (const float*)d_in[16];
    const float* prior_b = (const float*)d_in[17];
    const float* post_w  = (const float*)d_in[18];
    const float* post_b  = (const float*)d_in[19];
    const float* eps     = (const float*)d_in[20];
    float* out = (float*)d_out;

    float *b1, *b2, *b3, *b4, *feats, *w1T, *w2T, *w3T, *w4T, *fcT;
    cudaGetSymbolAddress((void**)&b1, g_b1);
    cudaGetSymbolAddress((void**)&b2, g_b2);
    cudaGetSymbolAddress((void**)&b3, g_b3);
    cudaGetSymbolAddress((void**)&b4, g_b4);
    cudaGetSymbolAddress((void**)&feats, g_feats);
    cudaGetSymbolAddress((void**)&w1T, g_w1T);
    cudaGetSymbolAddress((void**)&w2T, g_w2T);
    cudaGetSymbolAddress((void**)&w3T, g_w3T);
    cudaGetSymbolAddress((void**)&w4T, g_w4T);
    cudaGetSymbolAddress((void**)&fcT, g_fcT);

    // launch order arranged so the ncu-profiled launch (index 5) is conv2
    transpose_kernel<<<8, 256>>>(c1_w, w1T, 32, 48);               // 0
    conv1_kernel<<<dim3(NFR, 4), 256>>>(states, w1T, c1_b, b1);    // 1
    transpose_kernel<<<32, 256>>>(c2_w, w2T, 64, 512);             // 2
    transpose_kernel<<<64, 256>>>(c3_w, w3T, 128, 1024);           // 3
    transpose_kernel<<<128, 256>>>(c4_w, w4T, 256, 2048);          // 4

    // conv2: IC32 IH32 OC64 F1 OCW8 ICC4 S20 PS1360, 256 thr
    convN_kernel<32, 32, 64, 1, 8, 4, 20, 1360, 256>
        <<<NFR, 256>>>(b1, w2T, c2_b, b2);                         // 5 <- profiled
    // conv3: IC64 IH16 OC128 F2 OCW16 ICC4 S10 PS360, 256 thr
    convN_kernel<64, 16, 128, 2, 16, 4, 10, 360, 256>
        <<<NFR / 2, 256>>>(b2, w3T, c3_b, b3);                     // 6
    // conv4: IC128 IH8 OC256 F4 OCW16 ICC2 S9 PS208, 512 thr
    convN_kernel<128, 8, 256, 4, 16, 2, 9, 208, 512>
        <<<NFR / 4, 512>>>(b3, w4T, c4_b, b4);                     // 7

    transpose_kernel<<<256, 256>>>(fc_w, fcT, 256, 4096);          // 8
    fc_kernel<<<NFR / 16, 256>>>(b4, fcT, fc_b, feats);            // 9

    scan_kernel<<<BB, 384>>>(actions, feats, gru_wih, gru_whh, gru_bih, gru_bhh,
                             prior_w, prior_b, post_w, post_b, eps, out);  // 10
}

// round 3
// speedup vs baseline: 1.1377x; 1.0006x over previous
#include <cuda_runtime.h>

// ---------------- problem constants ----------------
#define BB 32
#define TT 64
#define NFR 2048          // B*T
#define AA 6
#define LL 32
#define HH 128
#define FD 256

// ---------------- scratch (static device memory; no allocations) ----------------
__device__ float g_b1[(size_t)NFR * 32 * 32 * 32];   // conv1 out
__device__ float g_b2[(size_t)NFR * 64 * 16 * 16];   // conv2 out
__device__ float g_b3[(size_t)NFR * 128 * 8 * 8];    // conv3 out
__device__ float g_b4[(size_t)NFR * 256 * 4 * 4];    // conv4 out
__device__ float g_feats[(size_t)NFR * FD];          // encoder features
__device__ float g_w1T[48 * 32];
__device__ float g_w2T[32 * 16 * 64];
__device__ float g_w3T[64 * 16 * 128];
__device__ float g_w4T[128 * 16 * 256];
__device__ float g_fcT[4096 * 256];

// packed fp32x2 FMA (sm_100+): d = a*b + c
__device__ __forceinline__ float2 ffma2(float2 a, float2 b, float2 c) {
#if defined(__CUDA_ARCH__) && (__CUDA_ARCH__ >= 1000)
    unsigned long long ua = *reinterpret_cast<unsigned long long*>(&a);
    unsigned long long ub = *reinterpret_cast<unsigned long long*>(&b);
    unsigned long long uc = *reinterpret_cast<unsigned long long*>(&c);
    unsigned long long ud;
    asm("fma.rn.f32x2 %0, %1, %2, %3;" : "=l"(ud) : "l"(ua), "l"(ub), "l"(uc));
    return *reinterpret_cast<float2*>(&ud);
#else
    c.x = fmaf(a.x, b.x, c.x);
    c.y = fmaf(a.y, b.y, c.y);
    return c;
#endif
}

// ---------------- weight transpose: w[oc][ict] -> wT[ict][oc] ----------------
__global__ void transpose_kernel(const float* __restrict__ w, float* __restrict__ wT,
                                 int OC, int ICT) {
    int total = OC * ICT;
    for (int idx = blockIdx.x * blockDim.x + threadIdx.x; idx < total;
         idx += gridDim.x * blockDim.x) {
        int oc = idx / ICT;
        int t  = idx % ICT;
        wT[t * OC + oc] = w[idx];
    }
}

// ---------------- conv1: (N,3,64,64) -> (N,32,32,32) ----------------
__global__ void conv1_kernel(const float* __restrict__ in, const float* __restrict__ wT,
                             const float* __restrict__ bias, float* __restrict__ out) {
    __shared__ __align__(16) float in_s[3 * 18 * 64];
    __shared__ __align__(16) float w_s[48 * 32];
    int tid = threadIdx.x;
    int n = blockIdx.x, s = blockIdx.y;
    const float* f = in + (size_t)n * 3 * 64 * 64;

    for (int i = tid; i < 3 * 18 * 64; i += 256) {
        int ch = i / (18 * 64);
        int r  = (i / 64) % 18;
        int c  = i % 64;
        int iy = 16 * s - 1 + r;
        in_s[i] = (iy >= 0 && iy < 64) ? f[ch * 4096 + iy * 64 + c] : 0.f;
    }
    for (int i = tid; i < 1536; i += 256) w_s[i] = wT[i];
    __syncthreads();

    int oyl = tid / 32, ox = tid % 32;
    float2 acc[16];
#pragma unroll
    for (int o = 0; o < 16; ++o) acc[o] = make_float2(0.f, 0.f);

    for (int ch = 0; ch < 3; ++ch) {
        for (int ky = 0; ky < 4; ++ky) {
            int r = 2 * oyl + ky;
            for (int kx = 0; kx < 4; ++kx) {
                int ix = 2 * ox + kx - 1;
                float v = (ix >= 0 && ix < 64) ? in_s[(ch * 18 + r) * 64 + ix] : 0.f;
                float2 v2 = make_float2(v, v);
                const float2* wr =
                    reinterpret_cast<const float2*>(&w_s[(ch * 16 + ky * 4 + kx) * 32]);
#pragma unroll
                for (int o = 0; o < 16; ++o) acc[o] = ffma2(v2, wr[o], acc[o]);
            }
        }
    }
    int oy = s * 8 + oyl;
#pragma unroll
    for (int o = 0; o < 16; ++o) {
        float r0 = acc[o].x + bias[2 * o];
        float r1 = acc[o].y + bias[2 * o + 1];
        out[(((size_t)n * 32 + 2 * o) * 32 + oy) * 32 + ox]     = r0 > 0.f ? r0 : 0.f;
        out[(((size_t)n * 32 + 2 * o + 1) * 32 + oy) * 32 + ox] = r1 > 0.f ? r1 : 0.f;
    }
}

// ---------------- generic conv (layers 2-4): parity-split smem, register-blocked ----
// Layout in smem per (channel, frame) plane: row r in [0, IH+2), parity p, x2 in [0, S)
//   idx = (y+1)*2*S + (x&1)*S + (x>>1) + 1 ; borders stay zero.
// Thread: P positions (g = lane + 32p over F*POS), OCW/2 float2 output channels.
template <int IC, int IH, int OC, int F, int OCW, int ICC, int S, int PS, int NTH>
__global__ void __launch_bounds__(NTH)
convN_kernel(const float* __restrict__ in, const float* __restrict__ wT,
             const float* __restrict__ bias, float* __restrict__ out) {
    constexpr int OW  = IH / 2;
    constexpr int POS = OW * OW;
    constexpr int P   = F * POS / 32;
    constexpr int OCP = OCW / 2;

    __shared__ __align__(16) float in_s[ICC * F * PS];
    __shared__ __align__(16) float w_s[ICC * 16 * OC];

    const int tid = threadIdx.x, lane = tid & 31, warp = tid >> 5;
    const int n0  = blockIdx.x * F;
    const int oc0 = warp * OCW;

    for (int i = tid; i < ICC * F * PS; i += NTH) in_s[i] = 0.f;

    int pbase[P];
#pragma unroll
    for (int p = 0; p < P; ++p) {
        int g = lane + 32 * p;
        int fr = g / POS, pg = g % POS;
        int oy = pg / OW, ox = pg % OW;
        pbase[p] = fr * PS + oy * 4 * S + ox;
    }

    float2 acc[P][OCP];
#pragma unroll
    for (int p = 0; p < P; ++p)
#pragma unroll
        for (int o = 0; o < OCP; ++o) acc[p][o] = make_float2(0.f, 0.f);

    for (int c0 = 0; c0 < IC; c0 += ICC) {
        __syncthreads();
        for (int i = tid; i < ICC * F * IH * IH; i += NTH) {
            int x  = i % IH;
            int y  = (i / IH) % IH;
            int fr = (i / (IH * IH)) % F;
            int c  = i / (IH * IH * F);
            float v = in[(((size_t)(n0 + fr)) * IC + (c0 + c)) * (IH * IH) + y * IH + x];
            in_s[(c * F + fr) * PS + (y + 1) * 2 * S + (x & 1) * S + (x >> 1) + 1] = v;
        }
        for (int i = tid; i < ICC * 16 * OC; i += NTH)
            w_s[i] = wT[(size_t)c0 * 16 * OC + i];
        __syncthreads();

#pragma unroll
        for (int icl = 0; icl < ICC; ++icl) {
            const float* A = in_s + icl * F * PS;
#pragma unroll
            for (int t = 0; t < 16; ++t) {
                const int ky = t >> 2, kx = t & 3;
                // kx -> (parity, dx): 0:(1,0) 1:(0,1) 2:(1,1) 3:(0,2)
                const int par = (kx == 0 || kx == 2) ? 1 : 0;
                const int dx  = (kx == 0) ? 0 : ((kx == 3) ? 2 : 1);
                const int koff = ky * 2 * S + par * S + dx;
                const float2* wr =
                    reinterpret_cast<const float2*>(&w_s[(icl * 16 + t) * OC + oc0]);
                float2 wv[OCP];
#pragma unroll
                for (int o = 0; o < OCP; ++o) wv[o] = wr[o];
#pragma unroll
                for (int p = 0; p < P; ++p) {
                    float a = A[pbase[p] + koff];
                    float2 a2 = make_float2(a, a);
#pragma unroll
                    for (int o = 0; o < OCP; ++o) acc[p][o] = ffma2(a2, wv[o], acc[p][o]);
                }
            }
        }
    }

#pragma unroll
    for (int p = 0; p < P; ++p) {
        int g = lane + 32 * p;
        int fr = g / POS, pg = g % POS;
        size_t base = (((size_t)(n0 + fr)) * OC + oc0) * POS + pg;
#pragma unroll
        for (int o = 0; o < OCP; ++o) {
            float r0 = acc[p][o].x + bias[oc0 + 2 * o];
            float r1 = acc[p][o].y + bias[oc0 + 2 * o + 1];
            out[base + (size_t)(2 * o) * POS]     = fmaxf(r0, 0.f);
            out[base + (size_t)(2 * o + 1) * POS] = fmaxf(r1, 0.f);
        }
    }
}

// ---------------- FC: feats[n][fd] = b4[n][:4096] . fcT[:,fd] + b ----------------
// 256 threads: tid%128 -> fd float2 column, tid/128 -> frame half. 16 frames/block.
__global__ void __launch_bounds__(256) fc_kernel(const float* __restrict__ inp,
                                                 const float* __restrict__ fcT,
                                                 const float* __restrict__ fcb,
                                                 float* __restrict__ feats) {
    constexpr int NPB = 16, KC = 128;
    __shared__ float in_s[NPB * KC];
    int tid = threadIdx.x;
    int fd2 = tid & 127;
    int half = tid >> 7;
    int n0 = blockIdx.x * NPB;
    const float2* fcT2 = reinterpret_cast<const float2*>(fcT);

    float2 acc[8];
#pragma unroll
    for (int nn = 0; nn < 8; ++nn) acc[nn] = make_float2(0.f, 0.f);

    for (int k0 = 0; k0 < 4096; k0 += KC) {
        __syncthreads();
        for (int i = tid; i < NPB * KC; i += 256) {
            int nn = i / KC, kk = i % KC;
            in_s[i] = inp[(size_t)(n0 + nn) * 4096 + k0 + kk];
        }
        __syncthreads();
        for (int kk = 0; kk < KC; ++kk) {
            float2 w = fcT2[(size_t)(k0 + kk) * 128 + fd2];
#pragma unroll
            for (int nn = 0; nn < 8; ++nn) {
                float v = in_s[(half * 8 + nn) * KC + kk];
                acc[nn] = ffma2(make_float2(v, v), w, acc[nn]);
            }
        }
    }
    float2 bv = reinterpret_cast<const float2*>(fcb)[fd2];
#pragma unroll
    for (int nn = 0; nn < 8; ++nn) {
        size_t o = (size_t)(n0 + half * 8 + nn) * 256 + 2 * fd2;
        feats[o]     = acc[nn].x + bv.x;
        feats[o + 1] = acc[nn].y + bv.y;
    }
}

// ---------------- sequential scan: GRU + prior/post + reparam ----------------
__global__ void scan_kernel(const float* __restrict__ actions, const float* __restrict__ feats,
                            const float* __restrict__ wih, const float* __restrict__ whh,
                            const float* __restrict__ bih, const float* __restrict__ bhh,
                            const float* __restrict__ pw, const float* __restrict__ pb,
                            const float* __restrict__ qw, const float* __restrict__ qb,
                            const float* __restrict__ eps, float* __restrict__ out) {
    int b = blockIdx.x, tid = threadIdx.x;
    __shared__ float x_s[40];
    __shared__ __align__(16) float h_s[HH];
    __shared__ __align__(16) float f_s[FD];
    __shared__ float gi_s[3 * HH], gh_s[3 * HH];
    __shared__ float p_s[2 * LL], q_s[2 * LL];

    if (tid < LL) x_s[tid] = 0.f;
    if (tid < HH) h_s[tid] = 0.f;

    float* out_mup = out;
    float* out_lvp = out + (size_t)NFR * LL;
    float* out_muq = out + (size_t)NFR * LL * 2;
    float* out_lvq = out + (size_t)NFR * LL * 3;
    float* out_h   = out + (size_t)NFR * LL * 4;
    float* out_z   = out + (size_t)NFR * LL * 4 + (size_t)NFR * HH;

    for (int t = 0; t < TT; ++t) {
        int bt = b * TT + t;
        if (tid >= LL && tid < LL + AA) x_s[tid] = actions[(size_t)bt * AA + (tid - LL)];
        if (tid < FD) f_s[tid] = feats[(size_t)bt * FD + tid];
        __syncthreads();

        {
            int j = tid;
            float gi = bih[j];
            const float* wr = wih + j * (LL + AA);
#pragma unroll
            for (int k = 0; k < LL + AA; ++k) gi = fmaf(x_s[k], wr[k], gi);

            float gh = bhh[j];
            const float4* w4 = reinterpret_cast<const float4*>(whh + (size_t)j * HH);
            float s0 = 0.f, s1 = 0.f, s2 = 0.f, s3 = 0.f;
#pragma unroll
            for (int k = 0; k < HH / 4; ++k) {
                float4 w = w4[k];
                s0 = fmaf(h_s[4 * k + 0], w.x, s0);
                s1 = fmaf(h_s[4 * k + 1], w.y, s1);
                s2 = fmaf(h_s[4 * k + 2], w.z, s2);
                s3 = fmaf(h_s[4 * k + 3], w.w, s3);
            }
            gh += (s0 + s1) + (s2 + s3);
            gi_s[j] = gi;
            gh_s[j] = gh;
        }
        __syncthreads();

        if (tid < HH) {
            int u = tid;
            float r  = 1.f / (1.f + expf(-(gi_s[u] + gh_s[u])));
            float zz = 1.f / (1.f + expf(-(gi_s[u + HH] + gh_s[u + HH])));
            float nn = tanhf(gi_s[u + 2 * HH] + r * gh_s[u + 2 * HH]);
            h_s[u] = (1.f - zz) * nn + zz * h_s[u];
        }
        __syncthreads();

        if (tid < 2 * LL) {
            int j = tid;
            const float4* w4 = reinterpret_cast<const float4*>(pw + (size_t)j * HH);
            float s0 = 0.f, s1 = 0.f, s2 = 0.f, s3 = 0.f;
#pragma unroll
            for (int k = 0; k < HH / 4; ++k) {
                float4 w = w4[k];
                s0 = fmaf(h_s[4 * k + 0], w.x, s0);
                s1 = fmaf(h_s[4 * k + 1], w.y, s1);
                s2 = fmaf(h_s[4 * k + 2], w.z, s2);
                s3 = fmaf(h_s[4 * k + 3], w.w, s3);
            }
            p_s[j] = pb[j] + (s0 + s1) + (s2 + s3);
        } else if (tid < 4 * LL) {
            int j = tid - 2 * LL;
            const float4* w4 = reinterpret_cast<const float4*>(qw + (size_t)j * (HH + FD));
            float s0 = 0.f, s1 = 0.f, s2 = 0.f, s3 = 0.f;
#pragma unroll
            for (int k = 0; k < HH / 4; ++k) {
                float4 w = w4[k];
                s0 = fmaf(h_s[4 * k + 0], w.x, s0);
                s1 = fmaf(h_s[4 * k + 1], w.y, s1);
                s2 = fmaf(h_s[4 * k + 2], w.z, s2);
                s3 = fmaf(h_s[4 * k + 3], w.w, s3);
            }
#pragma unroll
            for (int k = 0; k < FD / 4; ++k) {
                float4 w = w4[HH / 4 + k];
                s0 = fmaf(f_s[4 * k + 0], w.x, s0);
                s1 = fmaf(f_s[4 * k + 1], w.y, s1);
                s2 = fmaf(f_s[4 * k + 2], w.z, s2);
                s3 = fmaf(f_s[4 * k + 3], w.w, s3);
            }
            q_s[j] = qb[j] + (s0 + s1) + (s2 + s3);
        }
        __syncthreads();

        if (tid < HH) out_h[(size_t)bt * HH + tid] = h_s[tid];
        if (tid < LL) {
            int l = tid;
            out_mup[(size_t)bt * LL + l] = p_s[l];
            out_lvp[(size_t)bt * LL + l] = p_s[l + LL];
            float muq = q_s[l], lvq = q_s[l + LL];
            out_muq[(size_t)bt * LL + l] = muq;
            out_lvq[(size_t)bt * LL + l] = lvq;
            float z = muq + expf(0.5f * lvq) * eps[(size_t)bt * LL + l];
            out_z[(size_t)bt * LL + l] = z;
            x_s[l] = z;
        }
        __syncthreads();
    }
}

// ---------------- launch ----------------
extern "C" void kernel_launch(void* const* d_in, const int* in_sizes, int n_in,
                              void* d_out, int out_size) {
    const float* states  = (const float*)d_in[0];
    const float* actions = (const float*)d_in[1];
    const float* c1_w = (const float*)d_in[2];
    const float* c1_b = (const float*)d_in[3];
    const float* c2_w = (const float*)d_in[4];
    const float* c2_b = (const float*)d_in[5];
    const float* c3_w = (const float*)d_in[6];
    const float* c3_b = (const float*)d_in[7];
    const float* c4_w = (const float*)d_in[8];
    const float* c4_b = (const float*)d_in[9];
    const float* fc_w = (const float*)d_in[10];
    const float* fc_b = (const float*)d_in[11];
    const float* gru_wih = (const float*)d_in[12];
    const float* gru_whh = (const float*)d_in[13];
    const float* gru_bih = (const float*)d_in[14];
    const float* gru_bhh = (const float*)d_in[15];
    const float* prior_w = (const float*)d_in[16];
    const float* prior_b = (const float*)d_in[17];
    const float* post_w  = (const float*)d_in[18];
    const float* post_b  = (const float*)d_in[19];
    const float* eps     = (const float*)d_in[20];
    float* out = (float*)d_out;

    float *b1, *b2, *b3, *b4, *feats, *w1T, *w2T, *w3T, *w4T, *fcT;
    cudaGetSymbolAddress((void**)&b1, g_b1);
    cudaGetSymbolAddress((void**)&b2, g_b2);
    cudaGetSymbolAddress((void**)&b3, g_b3);
    cudaGetSymbolAddress((void**)&b4, g_b4);
    cudaGetSymbolAddress((void**)&feats, g_feats);
    cudaGetSymbolAddress((void**)&w1T, g_w1T);
    cudaGetSymbolAddress((void**)&w2T, g_w2T);
    cudaGetSymbolAddress((void**)&w3T, g_w3T);
    cudaGetSymbolAddress((void**)&w4T, g_w4T);
    cudaGetSymbolAddress((void**)&fcT, g_fcT);

    // launch order arranged so the ncu-profiled launch (index 5) is conv2
    transpose_kernel<<<8, 256>>>(c1_w, w1T, 32, 48);               // 0
    conv1_kernel<<<dim3(NFR, 4), 256>>>(states, w1T, c1_b, b1);    // 1
    transpose_kernel<<<32, 256>>>(c2_w, w2T, 64, 512);             // 2
    transpose_kernel<<<64, 256>>>(c3_w, w3T, 128, 1024);           // 3
    transpose_kernel<<<128, 256>>>(c4_w, w4T, 256, 2048);          // 4

    // conv2: IC32 IH32 OC64 F1 OCW8 ICC4 S20 PS1360, 256 thr
    convN_kernel<32, 32, 64, 1, 8, 4, 20, 1360, 256>
        <<<NFR, 256>>>(b1, w2T, c2_b, b2);                         // 5 <- profiled
    // conv3: IC64 IH16 OC128 F2 OCW16 ICC4 S10 PS360, 256 thr
    convN_kernel<64, 16, 128, 2, 16, 4, 10, 360, 256>
        <<<NFR / 2, 256>>>(b2, w3T, c3_b, b3);                     // 6
    // conv4: IC128 IH8 OC256 F4 OCW16 ICC2 S9 PS208, 512 thr
    convN_kernel<128, 8, 256, 4, 16, 2, 9, 208, 512>
        <<<NFR / 4, 512>>>(b3, w4T, c4_b, b4);                     // 7

    transpose_kernel<<<256, 256>>>(fc_w, fcT, 256, 4096);          // 8
    fc_kernel<<<NFR / 16, 256>>>(b4, fcT, fc_b, feats);            // 9

    scan_kernel<<<BB, 384>>>(actions, feats, gru_wih, gru_whh, gru_bih, gru_bhh,
                             prior_w, prior_b, post_w, post_b, eps, out);  // 10
}

// round 5
// speedup vs baseline: 1.8603x; 1.6352x over previous
#include <cuda_runtime.h>
#include <cuda_bf16.h>
#include <cstdint>

#define BB 32
#define TT 64
#define NFR 2048
#define AA 6
#define LL 32
#define HH 128
#define FD 256

// ---------------- static device scratch ----------------
__device__ float g_b1[(size_t)NFR * 32 * 32 * 32];
__device__ float g_b2[(size_t)NFR * 64 * 16 * 16];
__device__ float g_b3[(size_t)NFR * 128 * 8 * 8];
__device__ float g_b4[(size_t)NFR * 256 * 16];
__device__ float g_feats[(size_t)NFR * FD];
// bf16 hi/lo weight images, [oc][K] row-major
__device__ __align__(16) __nv_bfloat16 g_w2h[64 * 512],   g_w2l[64 * 512];
__device__ __align__(16) __nv_bfloat16 g_w3h[128 * 1024], g_w3l[128 * 1024];
__device__ __align__(16) __nv_bfloat16 g_w4h[256 * 2048], g_w4l[256 * 2048];
__device__ __align__(16) __nv_bfloat16 g_wfh[256 * 4096], g_wfl[256 * 4096];

// ---------------- helpers ----------------
__device__ __forceinline__ uint32_t smem_u32(const void* p) {
    uint32_t a;
    asm("{ .reg .u64 t; cvta.to.shared.u64 t, %1; cvt.u32.u64 %0, t; }" : "=r"(a) : "l"(p));
    return a;
}
__device__ __forceinline__ void bsplit(float v, __nv_bfloat16& h, __nv_bfloat16& l) {
    h = __float2bfloat16(v);
    l = __float2bfloat16(v - __bfloat162float(h));
}
__device__ __forceinline__ void ldmx4(uint32_t* r, uint32_t addr) {
    asm volatile("ldmatrix.sync.aligned.m8n8.x4.shared.b16 {%0,%1,%2,%3}, [%4];"
                 : "=r"(r[0]), "=r"(r[1]), "=r"(r[2]), "=r"(r[3]) : "r"(addr));
}
__device__ __forceinline__ void mma16816(float* c, const uint32_t* a, const uint32_t* b) {
    asm volatile(
        "mma.sync.aligned.m16n8k16.row.col.f32.bf16.bf16.f32 "
        "{%0,%1,%2,%3}, {%4,%5,%6,%7}, {%8,%9}, {%0,%1,%2,%3};"
        : "+f"(c[0]), "+f"(c[1]), "+f"(c[2]), "+f"(c[3])
        : "r"(a[0]), "r"(a[1]), "r"(a[2]), "r"(a[3]), "r"(b[0]), "r"(b[1]));
}
// packed fp32x2 FMA
__device__ __forceinline__ float2 ffma2(float2 a, float2 b, float2 c) {
    unsigned long long ua = *reinterpret_cast<unsigned long long*>(&a);
    unsigned long long ub = *reinterpret_cast<unsigned long long*>(&b);
    unsigned long long uc = *reinterpret_cast<unsigned long long*>(&c);
    unsigned long long ud;
    asm("fma.rn.f32x2 %0, %1, %2, %3;" : "=l"(ud) : "l"(ua), "l"(ub), "l"(uc));
    return *reinterpret_cast<float2*>(&ud);
}

// ---------------- weight splitter: w[oc][K] fp32 -> hi/lo bf16 ----------------
__global__ void pack_b_kernel(const float* __restrict__ w, __nv_bfloat16* __restrict__ bh,
                              __nv_bfloat16* __restrict__ bl, int total) {
    for (int idx = blockIdx.x * blockDim.x + threadIdx.x; idx < total;
         idx += gridDim.x * blockDim.x) {
        float v = w[idx];
        __nv_bfloat16 h, l;
        bsplit(v, h, l);
        bh[idx] = h;
        bl[idx] = l;
    }
}

// ---------------- conv1 (SIMT fp32): (N,3,64,64) -> (N,32,32,32) ----------------
__global__ void conv1_kernel(const float* __restrict__ in, const float* __restrict__ w,
                             const float* __restrict__ bias, float* __restrict__ out) {
    __shared__ __align__(16) float in_s[3 * 18 * 64];
    __shared__ __align__(16) float w_s[48 * 32];
    int tid = threadIdx.x;
    int n = blockIdx.x, s = blockIdx.y;
    const float* f = in + (size_t)n * 3 * 64 * 64;

    for (int i = tid; i < 3 * 18 * 64; i += 256) {
        int ch = i / (18 * 64);
        int r  = (i / 64) % 18;
        int c  = i % 64;
        int iy = 16 * s - 1 + r;
        in_s[i] = (iy >= 0 && iy < 64) ? f[ch * 4096 + iy * 64 + c] : 0.f;
    }
    for (int i = tid; i < 1536; i += 256) {   // transpose on the fly: w_s[t][oc]
        int t = i >> 5, oc = i & 31;
        w_s[i] = w[oc * 48 + t];
    }
    __syncthreads();

    int oyl = tid / 32, ox = tid % 32;
    float2 acc[16];
#pragma unroll
    for (int o = 0; o < 16; ++o) acc[o] = make_float2(0.f, 0.f);

    for (int ch = 0; ch < 3; ++ch)
        for (int ky = 0; ky < 4; ++ky) {
            int r = 2 * oyl + ky;
            for (int kx = 0; kx < 4; ++kx) {
                int ix = 2 * ox + kx - 1;
                float v = (ix >= 0 && ix < 64) ? in_s[(ch * 18 + r) * 64 + ix] : 0.f;
                float2 v2 = make_float2(v, v);
                const float2* wr =
                    reinterpret_cast<const float2*>(&w_s[(ch * 16 + ky * 4 + kx) * 32]);
#pragma unroll
                for (int o = 0; o < 16; ++o) acc[o] = ffma2(v2, wr[o], acc[o]);
            }
        }
    int oy = s * 8 + oyl;
#pragma unroll
    for (int o = 0; o < 16; ++o) {
        float r0 = acc[o].x + bias[2 * o];
        float r1 = acc[o].y + bias[2 * o + 1];
        out[(((size_t)n * 32 + 2 * o) * 32 + oy) * 32 + ox]     = fmaxf(r0, 0.f);
        out[(((size_t)n * 32 + 2 * o + 1) * 32 + oy) * 32 + ox] = fmaxf(r1, 0.f);
    }
}

// ---------------- tensor-core im2col GEMM (bf16 split, mma.sync) ----------------
// D[m0:128, n0:NT] = A[m, k] . W[n, k]^T ; K = IC*16 (conv, k = ic*16+ky*4+kx) or KTOT (fc)
template <int IC, int IH, int OC, int KTOT, int NT, bool IM2COL, bool RELU, int POS>
__global__ void __launch_bounds__(256)
mmagemm_kernel(const float* __restrict__ in, const __nv_bfloat16* __restrict__ gBh,
               const __nv_bfloat16* __restrict__ gBl, const float* __restrict__ bias,
               float* __restrict__ outp) {
    constexpr int AS  = 40;          // smem row stride (bf16) -> conflict-free ldmatrix
    constexpr int OW  = IH / 2;
    constexpr int WN  = NT / 2;      // warp N extent
    constexpr int NTI = WN / 8;      // n-tiles per warp
    constexpr int NPAIR = WN / 16;   // ldmatrix.x4 pairs per warp
    constexpr int NCH = KTOT / 32;

    __shared__ __align__(16) __nv_bfloat16 Ah[128 * AS];
    __shared__ __align__(16) __nv_bfloat16 Al[128 * AS];
    __shared__ __align__(16) __nv_bfloat16 Bh[NT * AS];
    __shared__ __align__(16) __nv_bfloat16 Bl[NT * AS];

    const int tid = threadIdx.x, lane = tid & 31, wid = tid >> 5;
    const int wm = wid & 3, wn = wid >> 2;
    const int m0 = blockIdx.x * 128;
    const int n0g = blockIdx.y * NT;

    const uint32_t ah_b = smem_u32(Ah), al_b = smem_u32(Al);
    const uint32_t bh_b = smem_u32(Bh), bl_b = smem_u32(Bl);

    float acc[2][NTI][4];
#pragma unroll
    for (int mt = 0; mt < 2; ++mt)
#pragma unroll
        for (int nt = 0; nt < NTI; ++nt)
#pragma unroll
            for (int q = 0; q < 4; ++q) acc[mt][nt][q] = 0.f;

    const int kcol = lane;            // 0..31 within chunk
    const int rowg = wid;             // 0..7

    for (int ch = 0; ch < NCH; ++ch) {
        if (ch) __syncthreads();

        // ---- stage A (gather + split) ----
        if (IM2COL) {
            const int k = ch * 32 + kcol;
            const int ic = k >> 4, tap = k & 15;
            const int ky = tap >> 2, kx = tap & 3;
            const float* plane = in + (size_t)ic * IH * IH;
#pragma unroll
            for (int j = 0; j < 16; ++j) {
                int r = rowg + j * 8;
                int m = m0 + r;
                int fr = m / POS;
                int pg = m & (POS - 1);
                int oy = pg / OW, ox = pg & (OW - 1);
                int iy = 2 * oy + ky - 1, ix = 2 * ox + kx - 1;
                float v = 0.f;
                if (iy >= 0 && iy < IH && ix >= 0 && ix < IH)
                    v = plane[(size_t)fr * IC * IH * IH + iy * IH + ix];
                __nv_bfloat16 h, l;
                bsplit(v, h, l);
                Ah[r * AS + kcol] = h;
                Al[r * AS + kcol] = l;
            }
        } else {
            const int k = ch * 32 + kcol;
#pragma unroll
            for (int j = 0; j < 16; ++j) {
                int r = rowg + j * 8;
                float v = in[(size_t)(m0 + r) * KTOT + k];
                __nv_bfloat16 h, l;
                bsplit(v, h, l);
                Ah[r * AS + kcol] = h;
                Al[r * AS + kcol] = l;
            }
        }
        // ---- stage B (uint4 copies of pre-split rows) ----
        for (int i = tid; i < NT * 4; i += 256) {
            int n = i >> 2, q = i & 3;
            size_t go = (size_t)(n0g + n) * KTOT + ch * 32 + q * 8;
            *(uint4*)&Bh[n * AS + q * 8] = *(const uint4*)&gBh[go];
            *(uint4*)&Bl[n * AS + q * 8] = *(const uint4*)&gBl[go];
        }
        __syncthreads();

        // ---- two K=16 steps ----
#pragma unroll
        for (int ks = 0; ks < 32; ks += 16) {
            uint32_t ahf[2][4], alf[2][4];
#pragma unroll
            for (int mt = 0; mt < 2; ++mt) {
                int row = wm * 32 + mt * 16 + (lane & 15);
                int koff = ks + ((lane >> 4) << 3);
                uint32_t off = (uint32_t)(row * AS + koff) * 2;
                ldmx4(ahf[mt], ah_b + off);
                ldmx4(alf[mt], al_b + off);
            }
#pragma unroll
            for (int np = 0; np < NPAIR; ++np) {
                uint32_t bhf[4], blf[4];
                int n = wn * WN + np * 16 + (lane & 7) + ((lane >> 4) << 3);
                int koff = ks + (((lane >> 3) & 1) << 3);
                uint32_t off = (uint32_t)(n * AS + koff) * 2;
                ldmx4(bhf, bh_b + off);
                ldmx4(blf, bl_b + off);
#pragma unroll
                for (int s = 0; s < 2; ++s) {
                    int nt = np * 2 + s;
#pragma unroll
                    for (int mt = 0; mt < 2; ++mt) {
                        mma16816(acc[mt][nt], ahf[mt], bhf + 2 * s);
                        mma16816(acc[mt][nt], ahf[mt], blf + 2 * s);
                        mma16816(acc[mt][nt], alf[mt], bhf + 2 * s);
                    }
                }
            }
        }
    }

    // ---- epilogue ----
#pragma unroll
    for (int mt = 0; mt < 2; ++mt) {
#pragma unroll
        for (int nt = 0; nt < NTI; ++nt) {
            int oc = n0g + wn * WN + nt * 8 + 2 * (lane & 3);
            float b0 = bias[oc], b1 = bias[oc + 1];
#pragma unroll
            for (int half = 0; half < 2; ++half) {
                int m = m0 + wm * 32 + mt * 16 + (lane >> 2) + half * 8;
                float x0 = acc[mt][nt][2 * half]     + b0;
                float x1 = acc[mt][nt][2 * half + 1] + b1;
                if (RELU) { x0 = fmaxf(x0, 0.f); x1 = fmaxf(x1, 0.f); }
                if (IM2COL) {
                    int fr = m / POS;
                    int pg = m & (POS - 1);
                    size_t base = ((size_t)fr * OC + oc) * POS + pg;
                    outp[base]       = x0;
                    outp[base + POS] = x1;
                } else {
                    *(float2*)&outp[(size_t)m * OC + oc] = make_float2(x0, x1);
                }
            }
        }
    }
}

// ---------------- sequential scan: GRU + prior/post + reparam ----------------
__global__ void scan_kernel(const float* __restrict__ actions, const float* __restrict__ feats,
                            const float* __restrict__ wih, const float* __restrict__ whh,
                            const float* __restrict__ bih, const float* __restrict__ bhh,
                            const float* __restrict__ pw, const float* __restrict__ pb,
                            const float* __restrict__ qw, const float* __restrict__ qb,
                            const float* __restrict__ eps, float* __restrict__ out) {
    int b = blockIdx.x, tid = threadIdx.x;
    __shared__ float x_s[40];
    __shared__ __align__(16) float h_s[HH];
    __shared__ __align__(16) float f_s[FD];
    __shared__ float gi_s[3 * HH], gh_s[3 * HH];
    __shared__ float p_s[2 * LL], q_s[2 * LL];

    if (tid < LL) x_s[tid] = 0.f;
    if (tid < HH) h_s[tid] = 0.f;

    float* out_mup = out;
    float* out_lvp = out + (size_t)NFR * LL;
    float* out_muq = out + (size_t)NFR * LL * 2;
    float* out_lvq = out + (size_t)NFR * LL * 3;
    float* out_h   = out + (size_t)NFR * LL * 4;
    float* out_z   = out + (size_t)NFR * LL * 4 + (size_t)NFR * HH;

    for (int t = 0; t < TT; ++t) {
        int bt = b * TT + t;
        if (tid >= LL && tid < LL + AA) x_s[tid] = actions[(size_t)bt * AA + (tid - LL)];
        if (tid < FD) f_s[tid] = feats[(size_t)bt * FD + tid];
        __syncthreads();

        {
            int j = tid;
            float gi = bih[j];
            const float* wr = wih + j * (LL + AA);
#pragma unroll
            for (int k = 0; k < LL + AA; ++k) gi = fmaf(x_s[k], wr[k], gi);

            float gh = bhh[j];
            const float4* w4 = reinterpret_cast<const float4*>(whh + (size_t)j * HH);
            float s0 = 0.f, s1 = 0.f, s2 = 0.f, s3 = 0.f;
#pragma unroll
            for (int k = 0; k < HH / 4; ++k) {
                float4 w = w4[k];
                s0 = fmaf(h_s[4 * k + 0], w.x, s0);
                s1 = fmaf(h_s[4 * k + 1], w.y, s1);
                s2 = fmaf(h_s[4 * k + 2], w.z, s2);
                s3 = fmaf(h_s[4 * k + 3], w.w, s3);
            }
            gh += (s0 + s1) + (s2 + s3);
            gi_s[j] = gi;
            gh_s[j] = gh;
        }
        __syncthreads();

        if (tid < HH) {
            int u = tid;
            float r  = 1.f / (1.f + expf(-(gi_s[u] + gh_s[u])));
            float zz = 1.f / (1.f + expf(-(gi_s[u + HH] + gh_s[u + HH])));
            float nn = tanhf(gi_s[u + 2 * HH] + r * gh_s[u + 2 * HH]);
            h_s[u] = (1.f - zz) * nn + zz * h_s[u];
        }
        __syncthreads();

        if (tid < 2 * LL) {
            int j = tid;
            const float4* w4 = reinterpret_cast<const float4*>(pw + (size_t)j * HH);
            float s0 = 0.f, s1 = 0.f, s2 = 0.f, s3 = 0.f;
#pragma unroll
            for (int k = 0; k < HH / 4; ++k) {
                float4 w = w4[k];
                s0 = fmaf(h_s[4 * k + 0], w.x, s0);
                s1 = fmaf(h_s[4 * k + 1], w.y, s1);
                s2 = fmaf(h_s[4 * k + 2], w.z, s2);
                s3 = fmaf(h_s[4 * k + 3], w.w, s3);
            }
            p_s[j] = pb[j] + (s0 + s1) + (s2 + s3);
        } else if (tid < 4 * LL) {
            int j = tid - 2 * LL;
            const float4* w4 = reinterpret_cast<const float4*>(qw + (size_t)j * (HH + FD));
            float s0 = 0.f, s1 = 0.f, s2 = 0.f, s3 = 0.f;
#pragma unroll
            for (int k = 0; k < HH / 4; ++k) {
                float4 w = w4[k];
                s0 = fmaf(h_s[4 * k + 0], w.x, s0);
                s1 = fmaf(h_s[4 * k + 1], w.y, s1);
                s2 = fmaf(h_s[4 * k + 2], w.z, s2);
                s3 = fmaf(h_s[4 * k + 3], w.w, s3);
            }
#pragma unroll
            for (int k = 0; k < FD / 4; ++k) {
                float4 w = w4[HH / 4 + k];
                s0 = fmaf(f_s[4 * k + 0], w.x, s0);
                s1 = fmaf(f_s[4 * k + 1], w.y, s1);
                s2 = fmaf(f_s[4 * k + 2], w.z, s2);
                s3 = fmaf(f_s[4 * k + 3], w.w, s3);
            }
            q_s[j] = qb[j] + (s0 + s1) + (s2 + s3);
        }
        __syncthreads();

        if (tid < HH) out_h[(size_t)bt * HH + tid] = h_s[tid];
        if (tid < LL) {
            int l = tid;
            out_mup[(size_t)bt * LL + l] = p_s[l];
            out_lvp[(size_t)bt * LL + l] = p_s[l + LL];
            float muq = q_s[l], lvq = q_s[l + LL];
            out_muq[(size_t)bt * LL + l] = muq;
            out_lvq[(size_t)bt * LL + l] = lvq;
            float z = muq + expf(0.5f * lvq) * eps[(size_t)bt * LL + l];
            out_z[(size_t)bt * LL + l] = z;
            x_s[l] = z;
        }
        __syncthreads();
    }
}

// ---------------- launch ----------------
extern "C" void kernel_launch(void* const* d_in, const int* in_sizes, int n_in,
                              void* d_out, int out_size) {
    const float* states  = (const float*)d_in[0];
    const float* actions = (const float*)d_in[1];
    const float* c1_w = (const float*)d_in[2];
    const float* c1_b = (const float*)d_in[3];
    const float* c2_w = (const float*)d_in[4];
    const float* c2_b = (const float*)d_in[5];
    const float* c3_w = (const float*)d_in[6];
    const float* c3_b = (const float*)d_in[7];
    const float* c4_w = (const float*)d_in[8];
    const float* c4_b = (const float*)d_in[9];
    const float* fc_w = (const float*)d_in[10];
    const float* fc_b = (const float*)d_in[11];
    const float* gru_wih = (const float*)d_in[12];
    const float* gru_whh = (const float*)d_in[13];
    const float* gru_bih = (const float*)d_in[14];
    const float* gru_bhh = (const float*)d_in[15];
    const float* prior_w = (const float*)d_in[16];
    const float* prior_b = (const float*)d_in[17];
    const float* post_w  = (const float*)d_in[18];
    const float* post_b  = (const float*)d_in[19];
    const float* eps     = (const float*)d_in[20];
    float* out = (float*)d_out;

    float *b1, *b2, *b3, *b4, *feats;
    __nv_bfloat16 *w2h, *w2l, *w3h, *w3l, *w4h, *w4l, *wfh, *wfl;
    cudaGetSymbolAddress((void**)&b1, g_b1);
    cudaGetSymbolAddress((void**)&b2, g_b2);
    cudaGetSymbolAddress((void**)&b3, g_b3);
    cudaGetSymbolAddress((void**)&b4, g_b4);
    cudaGetSymbolAddress((void**)&feats, g_feats);
    cudaGetSymbolAddress((void**)&w2h, g_w2h);  cudaGetSymbolAddress((void**)&w2l, g_w2l);
    cudaGetSymbolAddress((void**)&w3h, g_w3h);  cudaGetSymbolAddress((void**)&w3l, g_w3l);
    cudaGetSymbolAddress((void**)&w4h, g_w4h);  cudaGetSymbolAddress((void**)&w4l, g_w4l);
    cudaGetSymbolAddress((void**)&wfh, g_wfh);  cudaGetSymbolAddress((void**)&wfl, g_wfl);

    // 0
    pack_b_kernel<<<64, 256>>>(c2_w, w2h, w2l, 64 * 512);
    // 1
    conv1_kernel<<<dim3(NFR, 4), 256>>>(states, c1_w, c1_b, b1);
    // 2
    pack_b_kernel<<<128, 256>>>(c3_w, w3h, w3l, 128 * 1024);
    // 3 <- profiled: conv2 GEMM  (M=524288, N=64, K=512)
    mmagemm_kernel<32, 32, 64, 512, 64, true, true, 256>
        <<<dim3(4096, 1), 256>>>(b1, w2h, w2l, c2_b, b2);
    // 4
    pack_b_kernel<<<256, 256>>>(c4_w, w4h, w4l, 256 * 2048);
    // 5
    pack_b_kernel<<<512, 256>>>(fc_w, wfh, wfl, 256 * 4096);
    // 6: conv3 GEMM (M=131072, N=128, K=1024)
    mmagemm_kernel<64, 16, 128, 1024, 128, true, true, 64>
        <<<dim3(1024, 1), 256>>>(b2, w3h, w3l, c3_b, b3);
    // 7: conv4 GEMM (M=32768, N=256, K=2048)
    mmagemm_kernel<128, 8, 256, 2048, 128, true, true, 16>
        <<<dim3(256, 2), 256>>>(b3, w4h, w4l, c4_b, b4);
    // 8: fc GEMM (M=2048, N=256, K=4096)
    mmagemm_kernel<1, 2, 256, 4096, 128, false, false, 1>
        <<<dim3(16, 2), 256>>>(b4, wfh, wfl, fc_b, feats);
    // 9
    scan_kernel<<<BB, 384>>>(actions, feats, gru_wih, gru_whh, gru_bih, gru_bhh,
                             prior_w, prior_b, post_w, post_b, eps, out);
}

// round 6
// speedup vs baseline: 2.0922x; 1.1247x over previous
#include <cuda_runtime.h>
#include <cuda_bf16.h>
#include <cstdint>

#define BB 32
#define TT 64
#define NFR 2048
#define AA 6
#define LL 32
#define HH 128
#define FD 256

// ---------------- static device scratch ----------------
__device__ float g_b1[(size_t)NFR * 32 * 32 * 32];
__device__ float g_b2[(size_t)NFR * 64 * 16 * 16];
__device__ float g_b3[(size_t)NFR * 128 * 8 * 8];
__device__ float g_b4[(size_t)NFR * 256 * 16];
__device__ float g_feats[(size_t)NFR * FD];
// bf16 hi/lo weight images, [oc][K] row-major
__device__ __align__(16) __nv_bfloat16 g_w2h[64 * 512],   g_w2l[64 * 512];
__device__ __align__(16) __nv_bfloat16 g_w3h[128 * 1024], g_w3l[128 * 1024];
__device__ __align__(16) __nv_bfloat16 g_w4h[256 * 2048], g_w4l[256 * 2048];
__device__ __align__(16) __nv_bfloat16 g_wfh[256 * 4096], g_wfl[256 * 4096];

// ---------------- helpers ----------------
__device__ __forceinline__ uint32_t smem_u32(const void* p) {
    uint32_t a;
    asm("{ .reg .u64 t; cvta.to.shared.u64 t, %1; cvt.u32.u64 %0, t; }" : "=r"(a) : "l"(p));
    return a;
}
__device__ __forceinline__ void bsplit(float v, __nv_bfloat16& h, __nv_bfloat16& l) {
    h = __float2bfloat16(v);
    l = __float2bfloat16(v - __bfloat162float(h));
}
// pack two fp32 into (hi-pair, lo-pair) bf16x2 words
__device__ __forceinline__ void pack2(float v0, float v1, uint32_t& hw, uint32_t& lw) {
    __nv_bfloat16 h0, l0, h1, l1;
    bsplit(v0, h0, l0);
    bsplit(v1, h1, l1);
    hw = (uint32_t)__bfloat16_as_ushort(h0) | ((uint32_t)__bfloat16_as_ushort(h1) << 16);
    lw = (uint32_t)__bfloat16_as_ushort(l0) | ((uint32_t)__bfloat16_as_ushort(l1) << 16);
}
__device__ __forceinline__ void ldmx4(uint32_t* r, uint32_t addr) {
    asm volatile("ldmatrix.sync.aligned.m8n8.x4.shared.b16 {%0,%1,%2,%3}, [%4];"
                 : "=r"(r[0]), "=r"(r[1]), "=r"(r[2]), "=r"(r[3]) : "r"(addr));
}
__device__ __forceinline__ void mma16816(float* c, const uint32_t* a, const uint32_t* b) {
    asm volatile(
        "mma.sync.aligned.m16n8k16.row.col.f32.bf16.bf16.f32 "
        "{%0,%1,%2,%3}, {%4,%5,%6,%7}, {%8,%9}, {%0,%1,%2,%3};"
        : "+f"(c[0]), "+f"(c[1]), "+f"(c[2]), "+f"(c[3])
        : "r"(a[0]), "r"(a[1]), "r"(a[2]), "r"(a[3]), "r"(b[0]), "r"(b[1]));
}
// packed fp32x2 FMA
__device__ __forceinline__ float2 ffma2(float2 a, float2 b, float2 c) {
    unsigned long long ua = *reinterpret_cast<unsigned long long*>(&a);
    unsigned long long ub = *reinterpret_cast<unsigned long long*>(&b);
    unsigned long long uc = *reinterpret_cast<unsigned long long*>(&c);
    unsigned long long ud;
    asm("fma.rn.f32x2 %0, %1, %2, %3;" : "=l"(ud) : "l"(ua), "l"(ub), "l"(uc));
    return *reinterpret_cast<float2*>(&ud);
}

// ---------------- weight splitter ----------------
__global__ void pack_b_kernel(const float* __restrict__ w, __nv_bfloat16* __restrict__ bh,
                              __nv_bfloat16* __restrict__ bl, int total) {
    for (int idx = blockIdx.x * blockDim.x + threadIdx.x; idx < total;
         idx += gridDim.x * blockDim.x) {
        float v = w[idx];
        __nv_bfloat16 h, l;
        bsplit(v, h, l);
        bh[idx] = h;
        bl[idx] = l;
    }
}

// ---------------- conv1 (SIMT fp32): (N,3,64,64) -> (N,32,32,32) ----------------
__global__ void conv1_kernel(const float* __restrict__ in, const float* __restrict__ w,
                             const float* __restrict__ bias, float* __restrict__ out) {
    __shared__ __align__(16) float in_s[3 * 18 * 64];
    __shared__ __align__(16) float w_s[48 * 32];
    int tid = threadIdx.x;
    int n = blockIdx.x, s = blockIdx.y;
    const float* f = in + (size_t)n * 3 * 64 * 64;

    for (int i = tid; i < 3 * 18 * 64; i += 256) {
        int ch = i / (18 * 64);
        int r  = (i / 64) % 18;
        int c  = i % 64;
        int iy = 16 * s - 1 + r;
        in_s[i] = (iy >= 0 && iy < 64) ? f[ch * 4096 + iy * 64 + c] : 0.f;
    }
    for (int i = tid; i < 1536; i += 256) {
        int t = i >> 5, oc = i & 31;
        w_s[i] = w[oc * 48 + t];
    }
    __syncthreads();

    int oyl = tid / 32, ox = tid % 32;
    float2 acc[16];
#pragma unroll
    for (int o = 0; o < 16; ++o) acc[o] = make_float2(0.f, 0.f);

    for (int ch = 0; ch < 3; ++ch)
        for (int ky = 0; ky < 4; ++ky) {
            int r = 2 * oyl + ky;
            for (int kx = 0; kx < 4; ++kx) {
                int ix = 2 * ox + kx - 1;
                float v = (ix >= 0 && ix < 64) ? in_s[(ch * 18 + r) * 64 + ix] : 0.f;
                float2 v2 = make_float2(v, v);
                const float2* wr =
                    reinterpret_cast<const float2*>(&w_s[(ch * 16 + ky * 4 + kx) * 32]);
#pragma unroll
                for (int o = 0; o < 16; ++o) acc[o] = ffma2(v2, wr[o], acc[o]);
            }
        }
    int oy = s * 8 + oyl;
#pragma unroll
    for (int o = 0; o < 16; ++o) {
        float r0 = acc[o].x + bias[2 * o];
        float r1 = acc[o].y + bias[2 * o + 1];
        out[(((size_t)n * 32 + 2 * o) * 32 + oy) * 32 + ox]     = fmaxf(r0, 0.f);
        out[(((size_t)n * 32 + 2 * o + 1) * 32 + oy) * 32 + ox] = fmaxf(r1, 0.f);
    }
}

// ---------------- tensor-core im2col GEMM (bf16 split, mma.sync) ----------------
// D[m0:128, n0:NT] = A[m, k] . W[n, k]^T ; K = IC*16 (conv, k = ic*16+ky*4+kx) or KTOT (fc)
// A staging: thread = (row r = tid&127, k-half kg = tid>>7); each thread owns one ic
// plane per chunk and gathers its 16 taps with contiguous 4-float strips (coalesced).
template <int IC, int IH, int OC, int KTOT, int NT, bool IM2COL, bool RELU, int POS>
__global__ void __launch_bounds__(256)
mmagemm_kernel(const float* __restrict__ in, const __nv_bfloat16* __restrict__ gBh,
               const __nv_bfloat16* __restrict__ gBl, const float* __restrict__ bias,
               float* __restrict__ outp) {
    constexpr int AS  = 40;          // smem row stride (bf16) -> conflict-free ldmatrix
    constexpr int OW  = IH / 2;
    constexpr int WN  = NT / 2;      // warp N extent
    constexpr int NTI = WN / 8;
    constexpr int NPAIR = WN / 16;
    constexpr int NCH = KTOT / 32;

    __shared__ __align__(16) __nv_bfloat16 Ah[128 * AS];
    __shared__ __align__(16) __nv_bfloat16 Al[128 * AS];
    __shared__ __align__(16) __nv_bfloat16 Bh[NT * AS];
    __shared__ __align__(16) __nv_bfloat16 Bl[NT * AS];

    const int tid = threadIdx.x, lane = tid & 31, wid = tid >> 5;
    const int wm = wid & 3, wn = wid >> 2;
    const int m0 = blockIdx.x * 128;
    const int n0g = blockIdx.y * NT;

    const uint32_t ah_b = smem_u32(Ah), al_b = smem_u32(Al);
    const uint32_t bh_b = smem_u32(Bh), bl_b = smem_u32(Bl);

    float acc[2][NTI][4];
#pragma unroll
    for (int mt = 0; mt < 2; ++mt)
#pragma unroll
        for (int nt = 0; nt < NTI; ++nt)
#pragma unroll
            for (int q = 0; q < 4; ++q) acc[mt][nt][q] = 0.f;

    // ---- per-thread gather geometry (fixed across chunks) ----
    const int r  = tid & 127;
    const int kg = tid >> 7;             // 0/1: which 16-wide k half
    const int m  = m0 + r;
    const int fr = m / POS;
    const int pg = m & (POS - 1);
    const int oy = pg / OW, ox = pg & (OW - 1);
    const int iyb = 2 * oy - 1, ixb = 2 * ox - 1;

    for (int ch = 0; ch < NCH; ++ch) {
        if (ch) __syncthreads();

        uint32_t hw[8], lw[8];
        if (IM2COL) {
            const int ic = ch * 2 + kg;
            const float* plane = in + ((size_t)fr * IC + ic) * IH * IH;
#pragma unroll
            for (int ky = 0; ky < 4; ++ky) {
                int iy = iyb + ky;
                bool yok = (iy >= 0 && iy < IH);
                float v0 = 0.f, v1 = 0.f, v2 = 0.f, v3 = 0.f;
                if (yok) {
                    const float* rp = plane + iy * IH;
                    int i0 = ixb;
                    v0 = (i0 >= 0)          ? rp[i0]     : 0.f;
                    v1 =                       rp[i0 + 1];
                    v2 =                       rp[i0 + 2];
                    v3 = (i0 + 3 < IH)      ? rp[i0 + 3] : 0.f;
                }
                pack2(v0, v1, hw[ky * 2],     lw[ky * 2]);
                pack2(v2, v3, hw[ky * 2 + 1], lw[ky * 2 + 1]);
            }
        } else {
            const float* rp = in + (size_t)m * KTOT + ch * 32 + kg * 16;
#pragma unroll
            for (int q = 0; q < 4; ++q) {
                float4 v = *(const float4*)(rp + q * 4);
                pack2(v.x, v.y, hw[q * 2],     lw[q * 2]);
                pack2(v.z, v.w, hw[q * 2 + 1], lw[q * 2 + 1]);
            }
        }
        {
            uint32_t dof = r * AS + kg * 16;
            *(uint4*)&Ah[dof]     = *(uint4*)&hw[0];
            *(uint4*)&Ah[dof + 8] = *(uint4*)&hw[4];
            *(uint4*)&Al[dof]     = *(uint4*)&lw[0];
            *(uint4*)&Al[dof + 8] = *(uint4*)&lw[4];
        }
        // ---- stage B ----
        for (int i = tid; i < NT * 4; i += 256) {
            int n = i >> 2, q = i & 3;
            size_t go = (size_t)(n0g + n) * KTOT + ch * 32 + q * 8;
            *(uint4*)&Bh[n * AS + q * 8] = *(const uint4*)&gBh[go];
            *(uint4*)&Bl[n * AS + q * 8] = *(const uint4*)&gBl[go];
        }
        __syncthreads();

        // ---- two K=16 steps ----
#pragma unroll
        for (int ks = 0; ks < 32; ks += 16) {
            uint32_t ahf[2][4], alf[2][4];
#pragma unroll
            for (int mt = 0; mt < 2; ++mt) {
                int row = wm * 32 + mt * 16 + (lane & 15);
                int koff = ks + ((lane >> 4) << 3);
                uint32_t off = (uint32_t)(row * AS + koff) * 2;
                ldmx4(ahf[mt], ah_b + off);
                ldmx4(alf[mt], al_b + off);
            }
#pragma unroll
            for (int np = 0; np < NPAIR; ++np) {
                uint32_t bhf[4], blf[4];
                int n = wn * WN + np * 16 + (lane & 7) + ((lane >> 4) << 3);
                int koff = ks + (((lane >> 3) & 1) << 3);
                uint32_t off = (uint32_t)(n * AS + koff) * 2;
                ldmx4(bhf, bh_b + off);
                ldmx4(blf, bl_b + off);
#pragma unroll
                for (int s = 0; s < 2; ++s) {
                    int nt = np * 2 + s;
#pragma unroll
                    for (int mt = 0; mt < 2; ++mt) {
                        mma16816(acc[mt][nt], ahf[mt], bhf + 2 * s);
                        mma16816(acc[mt][nt], ahf[mt], blf + 2 * s);
                        mma16816(acc[mt][nt], alf[mt], bhf + 2 * s);
                    }
                }
            }
        }
    }

    // ---- epilogue ----
#pragma unroll
    for (int mt = 0; mt < 2; ++mt) {
#pragma unroll
        for (int nt = 0; nt < NTI; ++nt) {
            int oc = n0g + wn * WN + nt * 8 + 2 * (lane & 3);
            float b0 = bias[oc], b1 = bias[oc + 1];
#pragma unroll
            for (int half = 0; half < 2; ++half) {
                int mm = m0 + wm * 32 + mt * 16 + (lane >> 2) + half * 8;
                float x0 = acc[mt][nt][2 * half]     + b0;
                float x1 = acc[mt][nt][2 * half + 1] + b1;
                if (RELU) { x0 = fmaxf(x0, 0.f); x1 = fmaxf(x1, 0.f); }
                if (IM2COL) {
                    int frr = mm / POS;
                    int pgg = mm & (POS - 1);
                    size_t base = ((size_t)frr * OC + oc) * POS + pgg;
                    outp[base]       = x0;
                    outp[base + POS] = x1;
                } else {
                    *(float2*)&outp[(size_t)mm * OC + oc] = make_float2(x0, x1);
                }
            }
        }
    }
}

// ---------------- sequential scan: GRU + prior/post + reparam ----------------
__global__ void scan_kernel(const float* __restrict__ actions, const float* __restrict__ feats,
                            const float* __restrict__ wih, const float* __restrict__ whh,
                            const float* __restrict__ bih, const float* __restrict__ bhh,
                            const float* __restrict__ pw, const float* __restrict__ pb,
                            const float* __restrict__ qw, const float* __restrict__ qb,
                            const float* __restrict__ eps, float* __restrict__ out) {
    int b = blockIdx.x, tid = threadIdx.x;
    __shared__ float x_s[40];
    __shared__ __align__(16) float h_s[HH];
    __shared__ __align__(16) float f_s[FD];
    __shared__ float gi_s[3 * HH], gh_s[3 * HH];
    __shared__ float p_s[2 * LL], q_s[2 * LL];

    if (tid < LL) x_s[tid] = 0.f;
    if (tid < HH) h_s[tid] = 0.f;

    float* out_mup = out;
    float* out_lvp = out + (size_t)NFR * LL;
    float* out_muq = out + (size_t)NFR * LL * 2;
    float* out_lvq = out + (size_t)NFR * LL * 3;
    float* out_h   = out + (size_t)NFR * LL * 4;
    float* out_z   = out + (size_t)NFR * LL * 4 + (size_t)NFR * HH;

    for (int t = 0; t < TT; ++t) {
        int bt = b * TT + t;
        if (tid >= LL && tid < LL + AA) x_s[tid] = actions[(size_t)bt * AA + (tid - LL)];
        if (tid < FD) f_s[tid] = feats[(size_t)bt * FD + tid];
        __syncthreads();

        {
            int j = tid;
            float gi = bih[j];
            const float* wr = wih + j * (LL + AA);
#pragma unroll
            for (int k = 0; k < LL + AA; ++k) gi = fmaf(x_s[k], wr[k], gi);

            float gh = bhh[j];
            const float4* w4 = reinterpret_cast<const float4*>(whh + (size_t)j * HH);
            float s0 = 0.f, s1 = 0.f, s2 = 0.f, s3 = 0.f;
#pragma unroll
            for (int k = 0; k < HH / 4; ++k) {
                float4 w = w4[k];
                s0 = fmaf(h_s[4 * k + 0], w.x, s0);
                s1 = fmaf(h_s[4 * k + 1], w.y, s1);
                s2 = fmaf(h_s[4 * k + 2], w.z, s2);
                s3 = fmaf(h_s[4 * k + 3], w.w, s3);
            }
            gh += (s0 + s1) + (s2 + s3);
            gi_s[j] = gi;
            gh_s[j] = gh;
        }
        __syncthreads();

        if (tid < HH) {
            int u = tid;
            float r  = 1.f / (1.f + expf(-(gi_s[u] + gh_s[u])));
            float zz = 1.f / (1.f + expf(-(gi_s[u + HH] + gh_s[u + HH])));
            float nn = tanhf(gi_s[u + 2 * HH] + r * gh_s[u + 2 * HH]);
            h_s[u] = (1.f - zz) * nn + zz * h_s[u];
        }
        __syncthreads();

        if (tid < 2 * LL) {
            int j = tid;
            const float4* w4 = reinterpret_cast<const float4*>(pw + (size_t)j * HH);
            float s0 = 0.f, s1 = 0.f, s2 = 0.f, s3 = 0.f;
#pragma unroll
            for (int k = 0; k < HH / 4; ++k) {
                float4 w = w4[k];
                s0 = fmaf(h_s[4 * k + 0], w.x, s0);
                s1 = fmaf(h_s[4 * k + 1], w.y, s1);
                s2 = fmaf(h_s[4 * k + 2], w.z, s2);
                s3 = fmaf(h_s[4 * k + 3], w.w, s3);
            }
            p_s[j] = pb[j] + (s0 + s1) + (s2 + s3);
        } else if (tid < 4 * LL) {
            int j = tid - 2 * LL;
            const float4* w4 = reinterpret_cast<const float4*>(qw + (size_t)j * (HH + FD));
            float s0 = 0.f, s1 = 0.f, s2 = 0.f, s3 = 0.f;
#pragma unroll
            for (int k = 0; k < HH / 4; ++k) {
                float4 w = w4[k];
                s0 = fmaf(h_s[4 * k + 0], w.x, s0);
                s1 = fmaf(h_s[4 * k + 1], w.y, s1);
                s2 = fmaf(h_s[4 * k + 2], w.z, s2);
                s3 = fmaf(h_s[4 * k + 3], w.w, s3);
            }
#pragma unroll
            for (int k = 0; k < FD / 4; ++k) {
                float4 w = w4[HH / 4 + k];
                s0 = fmaf(f_s[4 * k + 0], w.x, s0);
                s1 = fmaf(f_s[4 * k + 1], w.y, s1);
                s2 = fmaf(f_s[4 * k + 2], w.z, s2);
                s3 = fmaf(f_s[4 * k + 3], w.w, s3);
            }
            q_s[j] = qb[j] + (s0 + s1) + (s2 + s3);
        }
        __syncthreads();

        if (tid < HH) out_h[(size_t)bt * HH + tid] = h_s[tid];
        if (tid < LL) {
            int l = tid;
            out_mup[(size_t)bt * LL + l] = p_s[l];
            out_lvp[(size_t)bt * LL + l] = p_s[l + LL];
            float muq = q_s[l], lvq = q_s[l + LL];
            out_muq[(size_t)bt * LL + l] = muq;
            out_lvq[(size_t)bt * LL + l] = lvq;
            float z = muq + expf(0.5f * lvq) * eps[(size_t)bt * LL + l];
            out_z[(size_t)bt * LL + l] = z;
            x_s[l] = z;
        }
        __syncthreads();
    }
}

// ---------------- launch ----------------
extern "C" void kernel_launch(void* const* d_in, const int* in_sizes, int n_in,
                              void* d_out, int out_size) {
    const float* states  = (const float*)d_in[0];
    const float* actions = (const float*)d_in[1];
    const float* c1_w = (const float*)d_in[2];
    const float* c1_b = (const float*)d_in[3];
    const float* c2_w = (const float*)d_in[4];
    const float* c2_b = (const float*)d_in[5];
    const float* c3_w = (const float*)d_in[6];
    const float* c3_b = (const float*)d_in[7];
    const float* c4_w = (const float*)d_in[8];
    const float* c4_b = (const float*)d_in[9];
    const float* fc_w = (const float*)d_in[10];
    const float* fc_b = (const float*)d_in[11];
    const float* gru_wih = (const float*)d_in[12];
    const float* gru_whh = (const float*)d_in[13];
    const float* gru_bih = (const float*)d_in[14];
    const float* gru_bhh = (const float*)d_in[15];
    const float* prior_w = (const float*)d_in[16];
    const float* prior_b = (const float*)d_in[17];
    const float* post_w  = (const float*)d_in[18];
    const float* post_b  = (const float*)d_in[19];
    const float* eps     = (const float*)d_in[20];
    float* out = (float*)d_out;

    float *b1, *b2, *b3, *b4, *feats;
    __nv_bfloat16 *w2h, *w2l, *w3h, *w3l, *w4h, *w4l, *wfh, *wfl;
    cudaGetSymbolAddress((void**)&b1, g_b1);
    cudaGetSymbolAddress((void**)&b2, g_b2);
    cudaGetSymbolAddress((void**)&b3, g_b3);
    cudaGetSymbolAddress((void**)&b4, g_b4);
    cudaGetSymbolAddress((void**)&feats, g_feats);
    cudaGetSymbolAddress((void**)&w2h, g_w2h);  cudaGetSymbolAddress((void**)&w2l, g_w2l);
    cudaGetSymbolAddress((void**)&w3h, g_w3h);  cudaGetSymbolAddress((void**)&w3l, g_w3l);
    cudaGetSymbolAddress((void**)&w4h, g_w4h);  cudaGetSymbolAddress((void**)&w4l, g_w4l);
    cudaGetSymbolAddress((void**)&wfh, g_wfh);  cudaGetSymbolAddress((void**)&wfl, g_wfl);

    // 0
    pack_b_kernel<<<64, 256>>>(c2_w, w2h, w2l, 64 * 512);
    // 1
    conv1_kernel<<<dim3(NFR, 4), 256>>>(states, c1_w, c1_b, b1);
    // 2
    pack_b_kernel<<<128, 256>>>(c3_w, w3h, w3l, 128 * 1024);
    // 3 <- profiled: conv2 GEMM  (M=524288, N=64, K=512)
    mmagemm_kernel<32, 32, 64, 512, 64, true, true, 256>
        <<<dim3(4096, 1), 256>>>(b1, w2h, w2l, c2_b, b2);
    // 4
    pack_b_kernel<<<256, 256>>>(c4_w, w4h, w4l, 256 * 2048);
    // 5
    pack_b_kernel<<<512, 256>>>(fc_w, wfh, wfl, 256 * 4096);
    // 6: conv3 GEMM (M=131072, N=128, K=1024)
    mmagemm_kernel<64, 16, 128, 1024, 128, true, true, 64>
        <<<dim3(1024, 1), 256>>>(b2, w3h, w3l, c3_b, b3);
    // 7: conv4 GEMM (M=32768, N=256, K=2048)
    mmagemm_kernel<128, 8, 256, 2048, 128, true, true, 16>
        <<<dim3(256, 2), 256>>>(b3, w4h, w4l, c4_b, b4);
    // 8: fc GEMM (M=2048, N=256, K=4096)
    mmagemm_kernel<1, 2, 256, 4096, 128, false, false, 1>
        <<<dim3(16, 2), 256>>>(b4, wfh, wfl, fc_b, feats);
    // 9
    scan_kernel<<<BB, 384>>>(actions, feats, gru_wih, gru_whh, gru_bih, gru_bhh,
                             prior_w, prior_b, post_w, post_b, eps, out);
}

// round 7
// speedup vs baseline: 2.5214x; 1.2051x over previous
#include <cuda_runtime.h>
#include <cuda_bf16.h>
#include <cstdint>

#define BB 32
#define TT 64
#define NFR 2048
#define AA 6
#define LL 32
#define HH 128
#define FD 256

// ---------------- static device scratch ----------------
__device__ float g_b1[(size_t)NFR * 32 * 32 * 32];
__device__ float g_b2[(size_t)NFR * 64 * 16 * 16];
__device__ float g_b3[(size_t)NFR * 128 * 8 * 8];
__device__ float g_b4[(size_t)NFR * 256 * 16];
__device__ float g_feats[(size_t)NFR * FD];
// bf16 hi/lo weight images, [oc][Kpad] row-major
__device__ __align__(16) __nv_bfloat16 g_w1h[32 * 64],    g_w1l[32 * 64];
__device__ __align__(16) __nv_bfloat16 g_w2h[64 * 512],   g_w2l[64 * 512];
__device__ __align__(16) __nv_bfloat16 g_w3h[128 * 1024], g_w3l[128 * 1024];
__device__ __align__(16) __nv_bfloat16 g_w4h[256 * 2048], g_w4l[256 * 2048];
__device__ __align__(16) __nv_bfloat16 g_wfh[256 * 4096], g_wfl[256 * 4096];

// ---------------- helpers ----------------
__device__ __forceinline__ uint32_t smem_u32(const void* p) {
    uint32_t a;
    asm("{ .reg .u64 t; cvta.to.shared.u64 t, %1; cvt.u32.u64 %0, t; }" : "=r"(a) : "l"(p));
    return a;
}
__device__ __forceinline__ void bsplit(float v, __nv_bfloat16& h, __nv_bfloat16& l) {
    h = __float2bfloat16(v);
    l = __float2bfloat16(v - __bfloat162float(h));
}
__device__ __forceinline__ void pack2(float v0, float v1, uint32_t& hw, uint32_t& lw) {
    __nv_bfloat16 h0, l0, h1, l1;
    bsplit(v0, h0, l0);
    bsplit(v1, h1, l1);
    hw = (uint32_t)__bfloat16_as_ushort(h0) | ((uint32_t)__bfloat16_as_ushort(h1) << 16);
    lw = (uint32_t)__bfloat16_as_ushort(l0) | ((uint32_t)__bfloat16_as_ushort(l1) << 16);
}
__device__ __forceinline__ void ldmx4(uint32_t* r, uint32_t addr) {
    asm volatile("ldmatrix.sync.aligned.m8n8.x4.shared.b16 {%0,%1,%2,%3}, [%4];"
                 : "=r"(r[0]), "=r"(r[1]), "=r"(r[2]), "=r"(r[3]) : "r"(addr));
}
__device__ __forceinline__ void mma16816(float* c, const uint32_t* a, const uint32_t* b) {
    asm volatile(
        "mma.sync.aligned.m16n8k16.row.col.f32.bf16.bf16.f32 "
        "{%0,%1,%2,%3}, {%4,%5,%6,%7}, {%8,%9}, {%0,%1,%2,%3};"
        : "+f"(c[0]), "+f"(c[1]), "+f"(c[2]), "+f"(c[3])
        : "r"(a[0]), "r"(a[1]), "r"(a[2]), "r"(a[3]), "r"(b[0]), "r"(b[1]));
}
__device__ __forceinline__ void cpasync16(uint32_t dst, const void* src) {
    asm volatile("cp.async.ca.shared.global [%0], [%1], 16;" :: "r"(dst), "l"(src));
}
#define CP_COMMIT() asm volatile("cp.async.commit_group;" ::: "memory")
#define CP_WAIT0()  asm volatile("cp.async.wait_group 0;" ::: "memory")

// ---------------- weight splitter (with K padding) ----------------
__global__ void pack_b_kernel(const float* __restrict__ w, __nv_bfloat16* __restrict__ bh,
                              __nv_bfloat16* __restrict__ bl, int OC, int Kr, int Kp) {
    int total = OC * Kp;
    for (int idx = blockIdx.x * blockDim.x + threadIdx.x; idx < total;
         idx += gridDim.x * blockDim.x) {
        int oc = idx / Kp, k = idx % Kp;
        float v = (k < Kr) ? w[(size_t)oc * Kr + k] : 0.f;
        __nv_bfloat16 h, l;
        bsplit(v, h, l);
        bh[idx] = h;
        bl[idx] = l;
    }
}

// ---------------- pipelined tensor-core im2col GEMM (bf16 split, mma.sync) -----------
// D[m0:128, n0:NT] = A[m,k] . W[n,k]^T ; conv k = ic*16+ky*4+kx (ic >= ICR -> 0)
// Pipeline: LDG A(ch+2) + cp.async B(ch+1, double buf) issued ahead of MMA(ch).
template <int ICR, int IH, int OC, int KTOT, int NT, bool IM2COL, bool RELU, int POS>
__global__ void __launch_bounds__(256)
mmagemm_kernel(const float* __restrict__ in, const __nv_bfloat16* __restrict__ gBh,
               const __nv_bfloat16* __restrict__ gBl, const float* __restrict__ bias,
               float* __restrict__ outp) {
    constexpr int AS  = 40;              // smem row stride (bf16) -> conflict-free
    constexpr int OW  = IH / 2;
    constexpr int WN  = NT / 2;
    constexpr int NTI = WN / 8;
    constexpr int NPAIR = WN / 16;
    constexpr int NCH = KTOT / 32;
    constexpr uint32_t BBUF = NT * AS * 2 * 2;   // bytes per B buffer (hi+lo)

    extern __shared__ __align__(16) char smem[];
    __nv_bfloat16* Ah = (__nv_bfloat16*)smem;            // 128*AS
    __nv_bfloat16* Al = Ah + 128 * AS;

    const uint32_t sb   = smem_u32(smem);
    const uint32_t ah_b = sb;
    const uint32_t al_b = sb + 128 * AS * 2;
    const uint32_t bbase = sb + 128 * AS * 4;

    const int tid = threadIdx.x, lane = tid & 31, wid = tid >> 5;
    const int wm = wid & 3, wn = wid >> 2;
    const int m0 = blockIdx.x * 128;
    const int n0g = blockIdx.y * NT;

    float acc[2][NTI][4];
#pragma unroll
    for (int mt = 0; mt < 2; ++mt)
#pragma unroll
        for (int nt = 0; nt < NTI; ++nt)
#pragma unroll
            for (int q = 0; q < 4; ++q) acc[mt][nt][q] = 0.f;

    // per-thread gather geometry
    const int r  = tid & 127;
    const int kg = tid >> 7;
    const int m  = m0 + r;
    const int fr = m / POS;
    const int pg = m & (POS - 1);
    const int oy = pg / OW, ox = pg & (OW - 1);
    const int iyb = 2 * oy - 1, ixb = 2 * ox - 1;

    float va[16];

    auto GATHER = [&](int ch) {
        if (IM2COL) {
            const int ic = ch * 2 + kg;
            const bool icok = (ic < ICR);
            const float* plane = in + ((size_t)fr * ICR + (icok ? ic : 0)) * IH * IH;
#pragma unroll
            for (int ky = 0; ky < 4; ++ky) {
                int iy = iyb + ky;
                bool yok = icok && iy >= 0 && iy < IH;
                const float* rp = plane + iy * IH;
                va[4 * ky + 0] = (yok && ixb >= 0)     ? rp[ixb]     : 0.f;
                va[4 * ky + 1] = yok                   ? rp[ixb + 1] : 0.f;
                va[4 * ky + 2] = yok                   ? rp[ixb + 2] : 0.f;
                va[4 * ky + 3] = (yok && ixb + 3 < IH) ? rp[ixb + 3] : 0.f;
            }
        } else {
            const float* rp = in + (size_t)m * KTOT + ch * 32 + kg * 16;
#pragma unroll
            for (int q = 0; q < 4; ++q) {
                float4 v = *(const float4*)(rp + q * 4);
                va[4 * q + 0] = v.x; va[4 * q + 1] = v.y;
                va[4 * q + 2] = v.z; va[4 * q + 3] = v.w;
            }
        }
    };
    auto STOREA = [&]() {
        uint32_t hw[8], lw[8];
#pragma unroll
        for (int q = 0; q < 8; ++q) pack2(va[2 * q], va[2 * q + 1], hw[q], lw[q]);
        uint32_t dof = r * AS + kg * 16;
        *(uint4*)&Ah[dof]     = *(uint4*)&hw[0];
        *(uint4*)&Ah[dof + 8] = *(uint4*)&hw[4];
        *(uint4*)&Al[dof]     = *(uint4*)&lw[0];
        *(uint4*)&Al[dof + 8] = *(uint4*)&lw[4];
    };
    auto STAGEB = [&](int ch) {
        uint32_t bd = bbase + (ch & 1) * BBUF;
        for (int i = tid; i < NT * 4; i += 256) {
            int n = i >> 2, q = i & 3;
            size_t go = (size_t)(n0g + n) * KTOT + ch * 32 + q * 8;
            cpasync16(bd + n * 80 + q * 16, gBh + go);
            cpasync16(bd + NT * 80 + n * 80 + q * 16, gBl + go);
        }
    };

    // ---- prologue ----
    GATHER(0);
    STAGEB(0);
    CP_COMMIT();
    STOREA();
    if (NCH > 1) GATHER(1);
    CP_WAIT0();
    __syncthreads();

    for (int ch = 0; ch < NCH; ++ch) {
        if (ch + 1 < NCH) STAGEB(ch + 1);
        CP_COMMIT();

        const uint32_t bh_b = bbase + (ch & 1) * BBUF;
        const uint32_t bl_b = bh_b + NT * 80;
#pragma unroll
        for (int ks = 0; ks < 32; ks += 16) {
            uint32_t ahf[2][4], alf[2][4];
#pragma unroll
            for (int mt = 0; mt < 2; ++mt) {
                int row = wm * 32 + mt * 16 + (lane & 15);
                int koff = ks + ((lane >> 4) << 3);
                uint32_t off = (uint32_t)(row * AS + koff) * 2;
                ldmx4(ahf[mt], ah_b + off);
                ldmx4(alf[mt], al_b + off);
            }
#pragma unroll
            for (int np = 0; np < NPAIR; ++np) {
                uint32_t bhf[4], blf[4];
                int n = wn * WN + np * 16 + (lane & 7) + ((lane >> 4) << 3);
                int koff = ks + (((lane >> 3) & 1) << 3);
                uint32_t off = (uint32_t)(n * AS + koff) * 2;
                ldmx4(bhf, bh_b + off);
                ldmx4(blf, bl_b + off);
#pragma unroll
                for (int s = 0; s < 2; ++s) {
                    int nt = np * 2 + s;
#pragma unroll
                    for (int mt = 0; mt < 2; ++mt) {
                        mma16816(acc[mt][nt], ahf[mt], bhf + 2 * s);
                        mma16816(acc[mt][nt], ahf[mt], blf + 2 * s);
                        mma16816(acc[mt][nt], alf[mt], bhf + 2 * s);
                    }
                }
            }
        }
        __syncthreads();                 // A reads done; safe to overwrite
        if (ch + 1 < NCH) {
            STOREA();                    // va holds chunk ch+1
            if (ch + 2 < NCH) GATHER(ch + 2);
            CP_WAIT0();
            __syncthreads();
        }
    }

    // ---- epilogue ----
#pragma unroll
    for (int mt = 0; mt < 2; ++mt) {
#pragma unroll
        for (int nt = 0; nt < NTI; ++nt) {
            int oc = n0g + wn * WN + nt * 8 + 2 * (lane & 3);
            float b0 = bias[oc], b1 = bias[oc + 1];
#pragma unroll
            for (int half = 0; half < 2; ++half) {
                int mm = m0 + wm * 32 + mt * 16 + (lane >> 2) + half * 8;
                float x0 = acc[mt][nt][2 * half]     + b0;
                float x1 = acc[mt][nt][2 * half + 1] + b1;
                if (RELU) { x0 = fmaxf(x0, 0.f); x1 = fmaxf(x1, 0.f); }
                if (IM2COL) {
                    int frr = mm / POS;
                    int pgg = mm & (POS - 1);
                    size_t base = ((size_t)frr * OC + oc) * POS + pgg;
                    outp[base]       = x0;
                    outp[base + POS] = x1;
                } else {
                    *(float2*)&outp[(size_t)mm * OC + oc] = make_float2(x0, x1);
                }
            }
        }
    }
}

// ---------------- sequential scan: GRU + prior/post + reparam ----------------
__global__ void scan_kernel(const float* __restrict__ actions, const float* __restrict__ feats,
                            const float* __restrict__ wih, const float* __restrict__ whh,
                            const float* __restrict__ bih, const float* __restrict__ bhh,
                            const float* __restrict__ pw, const float* __restrict__ pb,
                            const float* __restrict__ qw, const float* __restrict__ qb,
                            const float* __restrict__ eps, float* __restrict__ out) {
    int b = blockIdx.x, tid = threadIdx.x;
    __shared__ float x_s[40];
    __shared__ __align__(16) float h_s[HH];
    __shared__ __align__(16) float f_s[FD];
    __shared__ float gi_s[3 * HH], gh_s[3 * HH];
    __shared__ float p_s[2 * LL], q_s[2 * LL];

    if (tid < LL) x_s[tid] = 0.f;
    if (tid < HH) h_s[tid] = 0.f;

    float* out_mup = out;
    float* out_lvp = out + (size_t)NFR * LL;
    float* out_muq = out + (size_t)NFR * LL * 2;
    float* out_lvq = out + (size_t)NFR * LL * 3;
    float* out_h   = out + (size_t)NFR * LL * 4;
    float* out_z   = out + (size_t)NFR * LL * 4 + (size_t)NFR * HH;

    for (int t = 0; t < TT; ++t) {
        int bt = b * TT + t;
        if (tid >= LL && tid < LL + AA) x_s[tid] = actions[(size_t)bt * AA + (tid - LL)];
        if (tid < FD) f_s[tid] = feats[(size_t)bt * FD + tid];
        __syncthreads();

        {
            int j = tid;
            float gi = bih[j];
            const float* wr = wih + j * (LL + AA);
#pragma unroll
            for (int k = 0; k < LL + AA; ++k) gi = fmaf(x_s[k], wr[k], gi);

            float gh = bhh[j];
            const float4* w4 = reinterpret_cast<const float4*>(whh + (size_t)j * HH);
            float s0 = 0.f, s1 = 0.f, s2 = 0.f, s3 = 0.f;
#pragma unroll
            for (int k = 0; k < HH / 4; ++k) {
                float4 w = w4[k];
                s0 = fmaf(h_s[4 * k + 0], w.x, s0);
                s1 = fmaf(h_s[4 * k + 1], w.y, s1);
                s2 = fmaf(h_s[4 * k + 2], w.z, s2);
                s3 = fmaf(h_s[4 * k + 3], w.w, s3);
            }
            gh += (s0 + s1) + (s2 + s3);
            gi_s[j] = gi;
            gh_s[j] = gh;
        }
        __syncthreads();

        if (tid < HH) {
            int u = tid;
            float r  = 1.f / (1.f + expf(-(gi_s[u] + gh_s[u])));
            float zz = 1.f / (1.f + expf(-(gi_s[u + HH] + gh_s[u + HH])));
            float nn = tanhf(gi_s[u + 2 * HH] + r * gh_s[u + 2 * HH]);
            h_s[u] = (1.f - zz) * nn + zz * h_s[u];
        }
        __syncthreads();

        if (tid < 2 * LL) {
            int j = tid;
            const float4* w4 = reinterpret_cast<const float4*>(pw + (size_t)j * HH);
            float s0 = 0.f, s1 = 0.f, s2 = 0.f, s3 = 0.f;
#pragma unroll
            for (int k = 0; k < HH / 4; ++k) {
                float4 w = w4[k];
                s0 = fmaf(h_s[4 * k + 0], w.x, s0);
                s1 = fmaf(h_s[4 * k + 1], w.y, s1);
                s2 = fmaf(h_s[4 * k + 2], w.z, s2);
                s3 = fmaf(h_s[4 * k + 3], w.w, s3);
            }
            p_s[j] = pb[j] + (s0 + s1) + (s2 + s3);
        } else if (tid < 4 * LL) {
            int j = tid - 2 * LL;
            const float4* w4 = reinterpret_cast<const float4*>(qw + (size_t)j * (HH + FD));
            float s0 = 0.f, s1 = 0.f, s2 = 0.f, s3 = 0.f;
#pragma unroll
            for (int k = 0; k < HH / 4; ++k) {
                float4 w = w4[k];
                s0 = fmaf(h_s[4 * k + 0], w.x, s0);
                s1 = fmaf(h_s[4 * k + 1], w.y, s1);
                s2 = fmaf(h_s[4 * k + 2], w.z, s2);
                s3 = fmaf(h_s[4 * k + 3], w.w, s3);
            }
#pragma unroll
            for (int k = 0; k < FD / 4; ++k) {
                float4 w = w4[HH / 4 + k];
                s0 = fmaf(f_s[4 * k + 0], w.x, s0);
                s1 = fmaf(f_s[4 * k + 1], w.y, s1);
                s2 = fmaf(f_s[4 * k + 2], w.z, s2);
                s3 = fmaf(f_s[4 * k + 3], w.w, s3);
            }
            q_s[j] = qb[j] + (s0 + s1) + (s2 + s3);
        }
        __syncthreads();

        if (tid < HH) out_h[(size_t)bt * HH + tid] = h_s[tid];
        if (tid < LL) {
            int l = tid;
            out_mup[(size_t)bt * LL + l] = p_s[l];
            out_lvp[(size_t)bt * LL + l] = p_s[l + LL];
            float muq = q_s[l], lvq = q_s[l + LL];
            out_muq[(size_t)bt * LL + l] = muq;
            out_lvq[(size_t)bt * LL + l] = lvq;
            float z = muq + expf(0.5f * lvq) * eps[(size_t)bt * LL + l];
            out_z[(size_t)bt * LL + l] = z;
            x_s[l] = z;
        }
        __syncthreads();
    }
}

// ---------------- launch ----------------
extern "C" void kernel_launch(void* const* d_in, const int* in_sizes, int n_in,
                              void* d_out, int out_size) {
    const float* states  = (const float*)d_in[0];
    const float* actions = (const float*)d_in[1];
    const float* c1_w = (const float*)d_in[2];
    const float* c1_b = (const float*)d_in[3];
    const float* c2_w = (const float*)d_in[4];
    const float* c2_b = (const float*)d_in[5];
    const float* c3_w = (const float*)d_in[6];
    const float* c3_b = (const float*)d_in[7];
    const float* c4_w = (const float*)d_in[8];
    const float* c4_b = (const float*)d_in[9];
    const float* fc_w = (const float*)d_in[10];
    const float* fc_b = (const float*)d_in[11];
    const float* gru_wih = (const float*)d_in[12];
    const float* gru_whh = (const float*)d_in[13];
    const float* gru_bih = (const float*)d_in[14];
    const float* gru_bhh = (const float*)d_in[15];
    const float* prior_w = (const float*)d_in[16];
    const float* prior_b = (const float*)d_in[17];
    const float* post_w  = (const float*)d_in[18];
    const float* post_b  = (const float*)d_in[19];
    const float* eps     = (const float*)d_in[20];
    float* out = (float*)d_out;

    float *b1, *b2, *b3, *b4, *feats;
    __nv_bfloat16 *w1h, *w1l, *w2h, *w2l, *w3h, *w3l, *w4h, *w4l, *wfh, *wfl;
    cudaGetSymbolAddress((void**)&b1, g_b1);
    cudaGetSymbolAddress((void**)&b2, g_b2);
    cudaGetSymbolAddress((void**)&b3, g_b3);
    cudaGetSymbolAddress((void**)&b4, g_b4);
    cudaGetSymbolAddress((void**)&feats, g_feats);
    cudaGetSymbolAddress((void**)&w1h, g_w1h);  cudaGetSymbolAddress((void**)&w1l, g_w1l);
    cudaGetSymbolAddress((void**)&w2h, g_w2h);  cudaGetSymbolAddress((void**)&w2l, g_w2l);
    cudaGetSymbolAddress((void**)&w3h, g_w3h);  cudaGetSymbolAddress((void**)&w3l, g_w3l);
    cudaGetSymbolAddress((void**)&w4h, g_w4h);  cudaGetSymbolAddress((void**)&w4l, g_w4l);
    cudaGetSymbolAddress((void**)&wfh, g_wfh);  cudaGetSymbolAddress((void**)&wfl, g_wfl);

    auto c1 = mmagemm_kernel<3, 64, 32, 64, 32, true, true, 1024>;
    auto c2 = mmagemm_kernel<32, 32, 64, 512, 64, true, true, 256>;
    auto c3 = mmagemm_kernel<64, 16, 128, 1024, 128, true, true, 64>;
    auto c4 = mmagemm_kernel<128, 8, 256, 2048, 128, true, true, 16>;
    auto fc = mmagemm_kernel<1, 2, 256, 4096, 128, false, false, 1>;
    const int smA  = 128 * 40 * 2 * 2;                 // 20480
    const int sm1 = smA + 32 * 40 * 2 * 2 * 2;         // 30720
    const int sm2 = smA + 64 * 40 * 2 * 2 * 2;         // 40960
    const int sm3 = smA + 128 * 40 * 2 * 2 * 2;        // 61440
    cudaFuncSetAttribute(c1, cudaFuncAttributeMaxDynamicSharedMemorySize, sm1);
    cudaFuncSetAttribute(c2, cudaFuncAttributeMaxDynamicSharedMemorySize, sm2);
    cudaFuncSetAttribute(c3, cudaFuncAttributeMaxDynamicSharedMemorySize, sm3);
    cudaFuncSetAttribute(c4, cudaFuncAttributeMaxDynamicSharedMemorySize, sm3);
    cudaFuncSetAttribute(fc, cudaFuncAttributeMaxDynamicSharedMemorySize, sm3);

    // 0
    pack_b_kernel<<<8, 256>>>(c1_w, w1h, w1l, 32, 48, 64);
    // 1: conv1 GEMM (M=2097152, N=32, K=64)
    c1<<<dim3(16384, 1), 256, sm1>>>(states, w1h, w1l, c1_b, b1);
    // 2
    pack_b_kernel<<<64, 256>>>(c2_w, w2h, w2l, 64, 512, 512);
    // 3 <- profiled: conv2 GEMM (M=524288, N=64, K=512)
    c2<<<dim3(4096, 1), 256, sm2>>>(b1, w2h, w2l, c2_b, b2);
    // 4
    pack_b_kernel<<<128, 256>>>(c3_w, w3h, w3l, 128, 1024, 1024);
    // 5
    pack_b_kernel<<<256, 256>>>(c4_w, w4h, w4l, 256, 2048, 2048);
    // 6
    pack_b_kernel<<<512, 256>>>(fc_w, wfh, wfl, 256, 4096, 4096);
    // 7: conv3 GEMM (M=131072, N=128, K=1024)
    c3<<<dim3(1024, 1), 256, sm3>>>(b2, w3h, w3l, c3_b, b3);
    // 8: conv4 GEMM (M=32768, N=256, K=2048)
    c4<<<dim3(256, 2), 256, sm3>>>(b3, w4h, w4l, c4_b, b4);
    // 9: fc GEMM (M=2048, N=256, K=4096)
    fc<<<dim3(16, 2), 256, sm3>>>(b4, wfh, wfl, fc_b, feats);
    // 10
    scan_kernel<<<BB, 384>>>(actions, feats, gru_wih, gru_whh, gru_bih, gru_bhh,
                             prior_w, prior_b, post_w, post_b, eps, out);
}